// round 3
// baseline (speedup 1.0000x reference)
#include <cuda_runtime.h>
#include <cuda_bf16.h>
#include <cstdint>
#include <math.h>

#define Dk 128
#define Bk 1024
#define Rk 131072
#define NN 10
#define BN (Bk * NN)          // 10240
#define NCH 256               // 512-col chunks
#define NTILE 512
#define JBLK 16               // stage-2 j blocks
#define JW 640                // j per stage-2 block

typedef unsigned long long u64;
typedef unsigned int u32;

// ---------------- device scratch ----------------
__device__ float          g_feat[2][Bk * Dk];
__device__ __nv_bfloat16  g_featB[2][Bk * Dk];
__device__ __nv_bfloat16  g_qT[2][Rk * Dk];      // bf16 transposed queues [r][d]
__device__ float          g_candV[2][Bk * NCH * NN];
__device__ int            g_candI[2][Bk * NCH * NN];
__device__ int            g_topk[2][Bk * NN];
__device__ float          g_nnT[2][Dk * BN];     // gathered fp32 [d][j]
__device__ float          g_pS[2][Bk][JBLK];
__device__ float          g_pP[2][Bk][JBLK];

// ---------------- helpers ----------------
__device__ __forceinline__ u32 smem_u32(const void* p) {
    u32 a;
    asm("{ .reg .u64 t; cvta.to.shared.u64 t, %1; cvt.u32.u64 %0, t; }"
        : "=r"(a) : "l"(p));
    return a;
}
__device__ __forceinline__ void ldsm4(u32 &r0, u32 &r1, u32 &r2, u32 &r3, u32 addr) {
    asm volatile("ldmatrix.sync.aligned.m8n8.x4.shared.b16 {%0,%1,%2,%3}, [%4];"
        : "=r"(r0), "=r"(r1), "=r"(r2), "=r"(r3) : "r"(addr));
}
__device__ __forceinline__ void mma16816(float* d, const u32* a, u32 b0, u32 b1) {
    asm volatile("mma.sync.aligned.m16n8k16.row.col.f32.bf16.bf16.f32 "
        "{%0,%1,%2,%3}, {%4,%5,%6,%7}, {%8,%9}, {%0,%1,%2,%3};"
        : "+f"(d[0]), "+f"(d[1]), "+f"(d[2]), "+f"(d[3])
        : "r"(a[0]), "r"(a[1]), "r"(a[2]), "r"(a[3]), "r"(b0), "r"(b1));
}
__device__ __forceinline__ void ffma2(u64 &d, u64 a, u64 b) {
    asm("fma.rn.f32x2 %0, %1, %2, %0;" : "+l"(d) : "l"(a), "l"(b));
}
__device__ __forceinline__ u64 dupf(float f) {
    u64 r; unsigned u = __float_as_uint(f);
    asm("mov.b64 %0, {%1, %2};" : "=l"(r) : "r"(u), "r"(u));
    return r;
}
__device__ __forceinline__ float2 unpack2(u64 a) {
    float2 o;
    asm("mov.b64 {%0, %1}, %2;" : "=f"(o.x), "=f"(o.y) : "l"(a));
    return o;
}

// ---------------- 1. normalize rows (fp32 + bf16 copies) -----------------------
__global__ void normalize_kernel(const float* __restrict__ fX,
                                 const float* __restrict__ fY) {
    int side = blockIdx.y;
    int row = blockIdx.x;
    int d = threadIdx.x;
    const float* in = side ? fY : fX;
    float v = in[row * Dk + d];
    float sq = v * v;
    #pragma unroll
    for (int o = 16; o; o >>= 1) sq += __shfl_xor_sync(0xFFFFFFFFu, sq, o);
    __shared__ float ws[4];
    __shared__ float nrm;
    if ((d & 31) == 0) ws[d >> 5] = sq;
    __syncthreads();
    if (d == 0) nrm = sqrtf(ws[0] + ws[1] + ws[2] + ws[3]);
    __syncthreads();
    float nv = v / nrm;
    g_feat[side][row * Dk + d] = nv;
    g_featB[side][row * Dk + d] = __float2bfloat16(nv);
}

// ---------------- 2. transpose+convert queue -> bf16 [r][d] --------------------
__global__ void transpose_bf16_kernel(const float* __restrict__ qX,
                                      const float* __restrict__ qY) {
    int side = blockIdx.z;
    const float* src = side ? qX : qY;   // side 0 (feat X) uses queue_Y
    __shared__ float tile[32][33];
    int r0 = blockIdx.x * 32, d0 = blockIdx.y * 32;
    int tx = threadIdx.x, ty = threadIdx.y;
    #pragma unroll
    for (int i = 0; i < 4; ++i)
        tile[ty + i * 8][tx] = src[(size_t)(d0 + ty + i * 8) * Rk + r0 + tx];
    __syncthreads();
    __nv_bfloat16* dst = g_qT[side];
    #pragma unroll
    for (int i = 0; i < 4; ++i)
        dst[(size_t)(r0 + ty + i * 8) * Dk + d0 + tx] =
            __float2bfloat16(tile[tx][ty + i * 8]);
}

// ---------------- 3. HMMA sim GEMM + fused per-chunk top-10 --------------------
// CTA = one 512-col chunk of one side. B (512x128 bf16, swizzled) resident.
// Loop 32 M-tiles of 32 rows. 8 warps, warp tile 32x64 (accum 64 regs).
#define SM1_B  0                      // 131072 B
#define SM1_A  131072                 // 8192 B
#define SM1_S  139264                 // Ss: 32*520*4 = 66560 B
#define SM1_CV 205824                 // 32*8*10*4 = 10240 B
#define SM1_CI 216064                 // 10240 B
#define SMEM1  226304
#define SPITCH1 520

__global__ void __launch_bounds__(256, 1) simtopk_mma_kernel() {
    extern __shared__ char sm[];
    u32 sb = smem_u32(sm);
    float* Ss = reinterpret_cast<float*>(sm + SM1_S);
    float* Cv = reinterpret_cast<float*>(sm + SM1_CV);
    int*   Ci = reinterpret_cast<int*>(sm + SM1_CI);
    int t = threadIdx.x, w = t >> 5, lane = t & 31;
    int chunk = blockIdx.x, side = blockIdx.y;
    int warpN = w * 64;

    // load B chunk 512 x 128 bf16 with XOR-16B swizzle
    {
        const uint4* q4 = reinterpret_cast<const uint4*>(g_qT[side]);
        for (int i = t; i < 8192; i += 256) {
            int n = i >> 4, u = i & 15;
            *reinterpret_cast<uint4*>(sm + SM1_B + n * 256 + ((u ^ (n & 7)) << 4)) =
                q4[(size_t)(chunk * NTILE + n) * 16 + u];
        }
    }

    // per-lane ldmatrix address components
    u32 rowA = lane & 15;
    u32 selA = lane >> 4;
    u32 nrow = (lane & 7) | ((lane & 16) >> 1);
    u32 selB = (lane >> 3) & 1;

    const uint4* f4 = reinterpret_cast<const uint4*>(g_featB[side]);
    __syncthreads();

    for (int mt = 0; mt < 32; ++mt) {
        // load A 32x128 bf16 (2 uint4 per thread)
        {
            int i = t;
            #pragma unroll
            for (int rep = 0; rep < 2; ++rep, i += 256) {
                int m = i >> 4, u = i & 15;
                *reinterpret_cast<uint4*>(sm + SM1_A + m * 256 + ((u ^ (m & 7)) << 4)) =
                    f4[(size_t)(mt * 32 + m) * 16 + u];
            }
        }
        __syncthreads();

        float acc[2][8][4];
        #pragma unroll
        for (int i = 0; i < 2; ++i)
            #pragma unroll
            for (int j = 0; j < 8; ++j)
                #pragma unroll
                for (int k = 0; k < 4; ++k) acc[i][j][k] = 0.f;

        #pragma unroll
        for (int ks = 0; ks < 8; ++ks) {
            u32 a[2][4];
            #pragma unroll
            for (int mt2 = 0; mt2 < 2; ++mt2) {
                u32 addr = sb + SM1_A + (mt2 * 16 + rowA) * 256 +
                           ((((u32)ks * 2 + selA) ^ (rowA & 7)) << 4);
                ldsm4(a[mt2][0], a[mt2][1], a[mt2][2], a[mt2][3], addr);
            }
            #pragma unroll
            for (int p = 0; p < 4; ++p) {
                u32 b0, b1, b2, b3;
                u32 r = (u32)(warpN + p * 16) + nrow;
                u32 addr = sb + SM1_B + r * 256 +
                           ((((u32)ks * 2 + selB) ^ (r & 7)) << 4);
                ldsm4(b0, b1, b2, b3, addr);
                mma16816(acc[0][2 * p],     a[0], b0, b1);
                mma16816(acc[0][2 * p + 1], a[0], b2, b3);
                mma16816(acc[1][2 * p],     a[1], b0, b1);
                mma16816(acc[1][2 * p + 1], a[1], b2, b3);
            }
        }

        // store accum to Ss [32][520]
        {
            int qr = lane >> 2, qc = (lane & 3) * 2;
            #pragma unroll
            for (int mt2 = 0; mt2 < 2; ++mt2)
                #pragma unroll
                for (int nt = 0; nt < 8; ++nt) {
                    float* bp = Ss + (mt2 * 16 + qr) * SPITCH1 + warpN + nt * 8 + qc;
                    *reinterpret_cast<float2*>(bp) =
                        make_float2(acc[mt2][nt][0], acc[mt2][nt][1]);
                    *reinterpret_cast<float2*>(bp + 8 * SPITCH1) =
                        make_float2(acc[mt2][nt][2], acc[mt2][nt][3]);
                }
        }
        __syncthreads();

        // scan: 8 threads/row, each 64 cols -> smem top-10 list
        {
            int row = t >> 3, seg = t & 7;
            float* cv = Cv + (row * 8 + seg) * NN;
            int*   ci = Ci + (row * 8 + seg) * NN;
            #pragma unroll
            for (int k = 0; k < NN; ++k) { cv[k] = -1e30f; ci[k] = 0x7fffffff; }
            float tv9 = -1e30f;
            const float* sp = Ss + row * SPITCH1;
            for (int i = 0; i < 64; ++i) {
                int col = seg + (i << 3);
                float v = sp[col];
                if (v > tv9) {
                    int p = NN - 1;
                    while (p > 0 && cv[p - 1] < v) {
                        cv[p] = cv[p - 1]; ci[p] = ci[p - 1]; --p;
                    }
                    cv[p] = v; ci[p] = col;
                    tv9 = cv[NN - 1];
                }
            }
        }
        __syncthreads();

        // merge 80 candidates -> per-(row,chunk) top-10; Ss reused as scratch
        if (t < 32) {
            float* mv = Ss + t * 16;
            int*   mi = reinterpret_cast<int*>(Ss + 512 + t * 16);
            #pragma unroll
            for (int k = 0; k < NN; ++k) { mv[k] = -1e30f; mi[k] = 0x7fffffff; }
            float tv9 = -1e30f; int ti9 = 0x7fffffff;
            for (int s = 0; s < 8; ++s) {
                const float* cv = Cv + (t * 8 + s) * NN;
                const int*   ci = Ci + (t * 8 + s) * NN;
                for (int k = 0; k < NN; ++k) {
                    float v = cv[k];
                    if (v < tv9) break;
                    int id = ci[k];
                    if (v == tv9 && id >= ti9) continue;
                    int p = NN - 1;
                    while (p > 0 && (mv[p - 1] < v ||
                                     (mv[p - 1] == v && mi[p - 1] > id))) {
                        mv[p] = mv[p - 1]; mi[p] = mi[p - 1]; --p;
                    }
                    mv[p] = v; mi[p] = id;
                    tv9 = mv[NN - 1]; ti9 = mi[NN - 1];
                }
            }
            size_t gb = ((size_t)(mt * 32 + t) * NCH + chunk) * NN;
            #pragma unroll
            for (int k = 0; k < NN; ++k) {
                g_candV[side][gb + k] = mv[k];
                g_candI[side][gb + k] = chunk * NTILE + mi[k];
            }
        }
        __syncthreads();
    }
}

// ---------------- 4. reduce 2560 candidates -> top-10 per row ------------------
__global__ void topk_reduce_kernel() {
    __shared__ float v[NCH * NN];
    __shared__ int   id[NCH * NN];
    __shared__ float bv[256];
    __shared__ int   bp[256];
    int row = blockIdx.x;
    int side = blockIdx.y;
    int t = threadIdx.x;
    for (int i = t; i < NCH * NN; i += 256) {
        v[i] = g_candV[side][(size_t)row * (NCH * NN) + i];
        id[i] = g_candI[side][(size_t)row * (NCH * NN) + i];
    }
    __syncthreads();
    for (int k = 0; k < NN; ++k) {
        float best = -1e38f; int bpos = -1;
        for (int i = t; i < NCH * NN; i += 256) {
            float x = v[i];
            if (bpos < 0 || x > best || (x == best && id[i] < id[bpos])) { best = x; bpos = i; }
        }
        bv[t] = best; bp[t] = bpos;
        __syncthreads();
        for (int s = 128; s; s >>= 1) {
            if (t < s) {
                float xb = bv[t + s]; int xp = bp[t + s];
                bool take = (xp >= 0) && (bp[t] < 0 || xb > bv[t] ||
                             (xb == bv[t] && id[xp] < id[bp[t]]));
                if (take) { bv[t] = xb; bp[t] = xp; }
            }
            __syncthreads();
        }
        if (t == 0) { g_topk[side][row * NN + k] = id[bp[0]]; v[bp[0]] = -1e38f; }
        __syncthreads();
    }
}

// ---------------- 5. gather neighbor columns (exact fp32) ----------------------
__global__ void gather_kernel(const float* __restrict__ qX,
                              const float* __restrict__ qY) {
    int j = blockIdx.x * 256 + threadIdx.x;
    int d = blockIdx.y;
    int side = blockIdx.z;
    const float* Q = side ? qX : qY;
    int c = g_topk[side][j];
    g_nnT[side][d * BN + j] = Q[(size_t)d * Rk + c];
}

// ---------------- 6. stage-2 logits GEMM + fixed-max partial LSE ---------------
#define FP 132
#define SM2_F 0
#define SM2_J (64 * FP)
#define SM2_S (SM2_J + 128 * 64)
#define SM2_P (SM2_S + 64)
#define SMEM2_BYTES ((SM2_P + 64) * 4)

__global__ void __launch_bounds__(256, 2) lse_gemm_kernel() {
    extern __shared__ float s2[];
    float* F = s2 + SM2_F;
    float* J = s2 + SM2_J;
    float* accS = s2 + SM2_S;
    float* accP = s2 + SM2_P;
    int t = threadIdx.x;
    int tx = t & 15, ty = t >> 4;
    int rg = blockIdx.x, jb = blockIdx.y, side = blockIdx.z;

    {
        const float* feat = g_feat[side] + rg * 64 * Dk;
        for (int i = t; i < 64 * Dk; i += 256) {
            int r = i >> 7, d = i & 127;
            F[r * FP + d] = feat[i];
        }
        if (t < 64) { accS[t] = 0.f; accP[t] = 0.f; }
    }
    __syncthreads();

    const float4* nn4 = reinterpret_cast<const float4*>(g_nnT[side]);
    for (int jt = 0; jt < JW / 64; ++jt) {
        float4* J4 = reinterpret_cast<float4*>(J);
        #pragma unroll
        for (int i = 0; i < 8; ++i) {
            int lin = i * 256 + t;
            int d = lin >> 4, c4 = lin & 15;
            J4[d * 16 + c4] = nn4[(size_t)d * (BN / 4) + jb * (JW / 4) + jt * 16 + c4];
        }
        __syncthreads();

        u64 acc[4][2];
        #pragma unroll
        for (int r = 0; r < 4; ++r) { acc[r][0] = 0ull; acc[r][1] = 0ull; }
        const float* fb = F + (ty * 4) * FP;
        #pragma unroll 8
        for (int d = 0; d < Dk; ++d) {
            ulonglong2 q = *reinterpret_cast<const ulonglong2*>(J + d * 64 + tx * 4);
            #pragma unroll
            for (int r = 0; r < 4; ++r) {
                u64 fd = dupf(fb[r * FP + d]);
                ffma2(acc[r][0], q.x, fd);
                ffma2(acc[r][1], q.y, fd);
            }
        }

        int j0 = jb * JW + jt * 64 + tx * 4;
        #pragma unroll
        for (int r = 0; r < 4; ++r) {
            float2 a = unpack2(acc[r][0]);
            float2 b2 = unpack2(acc[r][1]);
            float vv[4] = { a.x, a.y, b2.x, b2.y };
            int rowg = rg * 64 + ty * 4 + r;
            float sE = 0.f, sP = 0.f;
            #pragma unroll
            for (int i = 0; i < 4; ++i) {
                float lg = vv[i] * 10.f;            // / TEMP
                sE += __expf(lg - 10.f);            // fixed max = 10 (cos<=1)
                unsigned dj = (unsigned)(j0 + i - rowg * NN);
                if (dj < (unsigned)NN) sP += lg;
            }
            #pragma unroll
            for (int o = 8; o; o >>= 1) {
                sE += __shfl_xor_sync(0xFFFFFFFFu, sE, o);
                sP += __shfl_xor_sync(0xFFFFFFFFu, sP, o);
            }
            if (tx == 0) { accS[ty * 4 + r] += sE; accP[ty * 4 + r] += sP; }
        }
        __syncthreads();
    }
    if (t < 64) {
        int rowg = rg * 64 + t;
        g_pS[side][rowg][jb] = accS[t];
        g_pP[side][rowg][jb] = accP[t];
    }
}

// ---------------- 7. combine partials -> loss ----------------------------------
__global__ void combine_kernel(float* __restrict__ out) {
    __shared__ float red[1024];
    int t = threadIdx.x;
    float term = 0.f;
    #pragma unroll
    for (int side = 0; side < 2; ++side) {
        float S = 0.f, P = 0.f;
        #pragma unroll
        for (int jb = 0; jb < JBLK; ++jb) { S += g_pS[side][t][jb]; P += g_pP[side][t][jb]; }
        term += P - (float)NN * (10.f + logf(S));
    }
    red[t] = term;
    __syncthreads();
    for (int s = 512; s; s >>= 1) {
        if (t < s) red[t] += red[t + s];
        __syncthreads();
    }
    if (t == 0) out[0] = -red[0] / (float)Bk;
}

// ---------------- 8. queue head columns ----------------------------------------
__global__ void qhead_kernel(float* __restrict__ out) {
    int c = blockIdx.x * 256 + threadIdx.x;
    int d = blockIdx.y;
    int side = blockIdx.z;
    out[1 + (size_t)side * Dk * Rk + (size_t)d * Rk + c] = g_feat[side][c * Dk + d];
}

// ---------------- launch --------------------------------------------------------
extern "C" void kernel_launch(void* const* d_in, const int* in_sizes, int n_in,
                              void* d_out, int out_size) {
    const float* fX = (const float*)d_in[0];
    const float* fY = (const float*)d_in[1];
    const float* qX = (const float*)d_in[2];
    const float* qY = (const float*)d_in[3];
    float* out = (float*)d_out;

    cudaFuncSetAttribute(simtopk_mma_kernel,
                         cudaFuncAttributeMaxDynamicSharedMemorySize, SMEM1);
    cudaFuncSetAttribute(lse_gemm_kernel,
                         cudaFuncAttributeMaxDynamicSharedMemorySize, SMEM2_BYTES);

    normalize_kernel<<<dim3(Bk, 2, 1), Dk>>>(fX, fY);
    transpose_bf16_kernel<<<dim3(Rk / 32, Dk / 32, 2), dim3(32, 8, 1)>>>(qX, qY);

    simtopk_mma_kernel<<<dim3(NCH, 2, 1), 256, SMEM1>>>();
    topk_reduce_kernel<<<dim3(Bk, 2, 1), 256>>>();
    gather_kernel<<<dim3(BN / 256, Dk, 2), 256>>>(qX, qY);
    lse_gemm_kernel<<<dim3(Bk / 64, JBLK, 2), 256, SMEM2_BYTES>>>();
    combine_kernel<<<1, 1024>>>(out);

    cudaMemcpyAsync(out + 1, qX, (size_t)Dk * Rk * sizeof(float),
                    cudaMemcpyDeviceToDevice, 0);
    cudaMemcpyAsync(out + 1 + (size_t)Dk * Rk, qY, (size_t)Dk * Rk * sizeof(float),
                    cudaMemcpyDeviceToDevice, 0);
    qhead_kernel<<<dim3(Bk / 256, Dk, 2), 256>>>(out);
}

// round 4
// speedup vs baseline: 1.1542x; 1.1542x over previous
#include <cuda_runtime.h>
#include <cstdint>
#include <math.h>

#define Dk 128
#define Bk 1024
#define Rk 131072
#define NN 10
#define BN (Bk * NN)          // 10240
#define NCH 256               // 512-col chunks
#define NTILE 512
#define JBLK 16               // stage-2 j blocks
#define JW 640                // j per stage-2 block

typedef unsigned long long u64;
typedef unsigned int u32;

// ---------------- device scratch ----------------
__device__ float g_feat[2][Bk * Dk];          // normalized fp32 feats [row][d]
__device__ u32   g_featQ[2][32][Bk];          // int8 feats packed [kc][row]
__device__ u32   g_qQ[2][32][Rk];             // int8 queue packed [kc][r]
__device__ float g_qscale[2][Rk];             // per-column maxabs
__device__ float g_qmul[2][Rk];               // 127/maxabs
__device__ float g_candV[2][Bk * NCH * NN];
__device__ int   g_candI[2][Bk * NCH * NN];
__device__ int   g_topk[2][Bk * NN];
__device__ float g_nnT[2][Dk * BN];           // gathered fp32 [d][j]
__device__ float g_pS[2][Bk][JBLK];
__device__ float g_pP[2][Bk][JBLK];

// ---------------- helpers ----------------
__device__ __forceinline__ void ffma2(u64 &d, u64 a, u64 b) {
    asm("fma.rn.f32x2 %0, %1, %2, %0;" : "+l"(d) : "l"(a), "l"(b));
}
__device__ __forceinline__ u64 dupf(float f) {
    u64 r; unsigned u = __float_as_uint(f);
    asm("mov.b64 %0, {%1, %2};" : "=l"(r) : "r"(u), "r"(u));
    return r;
}
__device__ __forceinline__ float2 unpack2(u64 a) {
    float2 o;
    asm("mov.b64 {%0, %1}, %2;" : "=f"(o.x), "=f"(o.y) : "l"(a));
    return o;
}

// ---------------- 1. normalize rows + int8 pack ---------------------------------
__global__ void normalize_kernel(const float* __restrict__ fX,
                                 const float* __restrict__ fY) {
    int side = blockIdx.y;
    int row = blockIdx.x;
    int d = threadIdx.x;
    const float* in = side ? fY : fX;
    float v = in[row * Dk + d];
    float sq = v * v;
    #pragma unroll
    for (int o = 16; o; o >>= 1) sq += __shfl_xor_sync(0xFFFFFFFFu, sq, o);
    __shared__ float ws[4], wm[4];
    __shared__ float nrm, smx;
    __shared__ unsigned char sb8[128];
    if ((d & 31) == 0) ws[d >> 5] = sq;
    __syncthreads();
    if (d == 0) nrm = sqrtf(ws[0] + ws[1] + ws[2] + ws[3]);
    __syncthreads();
    float nv = v / nrm;
    g_feat[side][row * Dk + d] = nv;
    float av = fabsf(nv);
    #pragma unroll
    for (int o = 16; o; o >>= 1) av = fmaxf(av, __shfl_xor_sync(0xFFFFFFFFu, av, o));
    if ((d & 31) == 0) wm[d >> 5] = av;
    __syncthreads();
    if (d == 0) smx = fmaxf(fmaxf(wm[0], wm[1]), fmaxf(wm[2], wm[3]));
    __syncthreads();
    int q = __float2int_rn(nv * (127.f / smx));
    sb8[d] = (unsigned char)(signed char)q;
    __syncthreads();
    if (d < 32) {
        u32 p = (u32)sb8[4 * d] | ((u32)sb8[4 * d + 1] << 8) |
                ((u32)sb8[4 * d + 2] << 16) | ((u32)sb8[4 * d + 3] << 24);
        g_featQ[side][d][row] = p;
    }
}

// ---------------- 2a. per-column maxabs of queue --------------------------------
__global__ void colmax_kernel(const float* __restrict__ qX,
                              const float* __restrict__ qY) {
    int side = blockIdx.y;
    const float* src = side ? qX : qY;   // side 0 (feat X) uses queue_Y
    int c = blockIdx.x * 256 + threadIdx.x;
    float mx = 1e-12f;
    for (int d = 0; d < Dk; ++d)
        mx = fmaxf(mx, fabsf(src[(size_t)d * Rk + c]));
    g_qscale[side][c] = mx;
    g_qmul[side][c] = 127.f / mx;
}

// ---------------- 2b. transpose + int8 quantize queue ---------------------------
__global__ void transposeQ_kernel(const float* __restrict__ qX,
                                  const float* __restrict__ qY) {
    int side = blockIdx.z;
    const float* src = side ? qX : qY;
    __shared__ float tile[32][33];
    int r0 = blockIdx.x * 32, d0 = blockIdx.y * 32;
    int tx = threadIdx.x, ty = threadIdx.y;
    #pragma unroll
    for (int i = 0; i < 4; ++i)
        tile[ty + i * 8][tx] = src[(size_t)(d0 + ty + i * 8) * Rk + r0 + tx];
    __syncthreads();
    float mul = g_qmul[side][r0 + tx];
    u32 p = 0;
    #pragma unroll
    for (int b = 0; b < 4; ++b) {
        int q = __float2int_rn(tile[ty * 4 + b][tx] * mul);
        p |= ((u32)(unsigned char)(signed char)q) << (8 * b);
    }
    g_qQ[side][(d0 >> 2) + ty][r0 + tx] = p;
}

// ---------------- 3. DP4A sim GEMM + fused per-chunk top-10 ---------------------
// CTA = one 512-col chunk, all 1024 rows (16 M-tiles of 64). 256 threads (16x16).
// Thread tile: 4 rows x 16 cols (2 col-passes held), 2 halves of 256 cols.
#define S1_B  0                       // Qs u32 [kc][512]  = 65536 B
#define S1_SC 65536                   // 512 floats        = 2048 B
#define S1_A  67584                   // As u32 [kc][64]   = 8192 B
#define S1_SS 75776                   // Ss [64][260] f32  = 66560 B
#define S1_CV 142336                  // 64*8*10 f32       = 20480 B
#define S1_CI 162816                  // 64*8*10 int       = 20480 B
#define SMEM1 183296
#define SP1 260

__global__ void __launch_bounds__(256, 1) simtopk_i8_kernel() {
    extern __shared__ char sm[];
    u32*   Qs = reinterpret_cast<u32*>(sm + S1_B);
    float* SC = reinterpret_cast<float*>(sm + S1_SC);
    u32*   As = reinterpret_cast<u32*>(sm + S1_A);
    float* Ss = reinterpret_cast<float*>(sm + S1_SS);
    float* Cv = reinterpret_cast<float*>(sm + S1_CV);
    int*   Ci = reinterpret_cast<int*>(sm + S1_CI);
    int t = threadIdx.x, tx = t & 15, ty = t >> 4;
    int chunk = blockIdx.x, side = blockIdx.y;

    // load B chunk: 32 kc x 512 u32 (coalesced per kc row)
    {
        for (int i = t; i < 4096; i += 256) {
            int kc = i >> 7, c4 = i & 127;
            reinterpret_cast<uint4*>(Qs + kc * 512)[c4] =
                reinterpret_cast<const uint4*>(&g_qQ[side][kc][chunk * NTILE])[c4];
        }
        for (int i = t; i < 512; i += 256)
            SC[i] = g_qscale[side][chunk * NTILE + i];
    }
    __syncthreads();

    for (int mt = 0; mt < 16; ++mt) {
        // load A tile: 32 kc x 64 rows u32
        for (int i = t; i < 512; i += 256) {
            int kc = i >> 4, r4 = i & 15;
            reinterpret_cast<uint4*>(As + kc * 64)[r4] =
                reinterpret_cast<const uint4*>(&g_featQ[side][kc][mt * 64])[r4];
        }
        for (int i = t; i < 64 * 8 * NN; i += 256) { Cv[i] = -1e30f; Ci[i] = 0x7fffffff; }
        __syncthreads();

        for (int h = 0; h < 2; ++h) {
            int acc[2][4][8];
            #pragma unroll
            for (int p = 0; p < 2; ++p)
                #pragma unroll
                for (int r = 0; r < 4; ++r)
                    #pragma unroll
                    for (int c = 0; c < 8; ++c) acc[p][r][c] = 0;

            int colb = h * 256;
            #pragma unroll 4
            for (int kc = 0; kc < 32; ++kc) {
                int f[4];
                #pragma unroll
                for (int r = 0; r < 4; ++r) f[r] = (int)As[kc * 64 + ty * 4 + r];
                #pragma unroll
                for (int p = 0; p < 2; ++p) {
                    const u32* qp = Qs + kc * 512 + colb + p * 128 + tx * 8;
                    uint4 qa = *reinterpret_cast<const uint4*>(qp);
                    uint4 qb = *reinterpret_cast<const uint4*>(qp + 4);
                    #pragma unroll
                    for (int r = 0; r < 4; ++r) {
                        acc[p][r][0] = __dp4a((int)qa.x, f[r], acc[p][r][0]);
                        acc[p][r][1] = __dp4a((int)qa.y, f[r], acc[p][r][1]);
                        acc[p][r][2] = __dp4a((int)qa.z, f[r], acc[p][r][2]);
                        acc[p][r][3] = __dp4a((int)qa.w, f[r], acc[p][r][3]);
                        acc[p][r][4] = __dp4a((int)qb.x, f[r], acc[p][r][4]);
                        acc[p][r][5] = __dp4a((int)qb.y, f[r], acc[p][r][5]);
                        acc[p][r][6] = __dp4a((int)qb.z, f[r], acc[p][r][6]);
                        acc[p][r][7] = __dp4a((int)qb.w, f[r], acc[p][r][7]);
                    }
                }
            }

            // write Ss (current half only, 64 x 256 @ pitch 260), scaled by col max
            #pragma unroll
            for (int p = 0; p < 2; ++p) {
                const float* scp = SC + colb + p * 128 + tx * 8;
                float4 s0 = *reinterpret_cast<const float4*>(scp);
                float4 s1 = *reinterpret_cast<const float4*>(scp + 4);
                #pragma unroll
                for (int r = 0; r < 4; ++r) {
                    float* dp = Ss + (ty * 4 + r) * SP1 + p * 128 + tx * 8;
                    dp[0] = (float)acc[p][r][0] * s0.x;
                    dp[1] = (float)acc[p][r][1] * s0.y;
                    dp[2] = (float)acc[p][r][2] * s0.z;
                    dp[3] = (float)acc[p][r][3] * s0.w;
                    dp[4] = (float)acc[p][r][4] * s1.x;
                    dp[5] = (float)acc[p][r][5] * s1.y;
                    dp[6] = (float)acc[p][r][6] * s1.z;
                    dp[7] = (float)acc[p][r][7] * s1.w;
                }
            }
            __syncthreads();

            // scan: 64 rows x 4 segs; each thread 64 cols of this half
            {
                int row = t >> 2, seg = t & 3;
                float* cv = Cv + (row * 8 + h * 4 + seg) * NN;
                int*   ci = Ci + (row * 8 + h * 4 + seg) * NN;
                float tv9 = -1e30f;
                const float* sp = Ss + row * SP1;
                for (int i = 0; i < 64; ++i) {
                    int col = seg + 4 * i;
                    float v = sp[col];
                    if (v > tv9) {
                        int p = NN - 1;
                        while (p > 0 && cv[p - 1] < v) {
                            cv[p] = cv[p - 1]; ci[p] = ci[p - 1]; --p;
                        }
                        cv[p] = v; ci[p] = colb + col;
                        tv9 = cv[NN - 1];
                    }
                }
            }
            __syncthreads();
        }

        // merge 8 lists -> top-10 per row (Ss reused as scratch)
        if (t < 64) {
            float* mv = Ss + t * 16;
            int*   mi = reinterpret_cast<int*>(Ss + 1024 + t * 16);
            #pragma unroll
            for (int k = 0; k < NN; ++k) { mv[k] = -1e30f; mi[k] = 0x7fffffff; }
            float tv9 = -1e30f; int ti9 = 0x7fffffff;
            for (int s = 0; s < 8; ++s) {
                const float* cv = Cv + (t * 8 + s) * NN;
                const int*   ci = Ci + (t * 8 + s) * NN;
                for (int k = 0; k < NN; ++k) {
                    float v = cv[k];
                    if (v < tv9) break;
                    int id = ci[k];
                    if (v == tv9 && id >= ti9) continue;
                    int p = NN - 1;
                    while (p > 0 && (mv[p - 1] < v ||
                                     (mv[p - 1] == v && mi[p - 1] > id))) {
                        mv[p] = mv[p - 1]; mi[p] = mi[p - 1]; --p;
                    }
                    mv[p] = v; mi[p] = id;
                    tv9 = mv[NN - 1]; ti9 = mi[NN - 1];
                }
            }
            size_t gb = ((size_t)(mt * 64 + t) * NCH + chunk) * NN;
            #pragma unroll
            for (int k = 0; k < NN; ++k) {
                g_candV[side][gb + k] = mv[k];
                g_candI[side][gb + k] = chunk * NTILE + mi[k];
            }
        }
        __syncthreads();
    }
}

// ---------------- 4. reduce 2560 candidates -> top-10 per row -------------------
__global__ void topk_reduce_kernel() {
    __shared__ float v[NCH * NN];
    __shared__ int   id[NCH * NN];
    __shared__ float bv[256];
    __shared__ int   bp[256];
    int row = blockIdx.x;
    int side = blockIdx.y;
    int t = threadIdx.x;
    for (int i = t; i < NCH * NN; i += 256) {
        v[i] = g_candV[side][(size_t)row * (NCH * NN) + i];
        id[i] = g_candI[side][(size_t)row * (NCH * NN) + i];
    }
    __syncthreads();
    for (int k = 0; k < NN; ++k) {
        float best = -1e38f; int bpos = -1;
        for (int i = t; i < NCH * NN; i += 256) {
            float x = v[i];
            if (bpos < 0 || x > best || (x == best && id[i] < id[bpos])) { best = x; bpos = i; }
        }
        bv[t] = best; bp[t] = bpos;
        __syncthreads();
        for (int s = 128; s; s >>= 1) {
            if (t < s) {
                float xb = bv[t + s]; int xp = bp[t + s];
                bool take = (xp >= 0) && (bp[t] < 0 || xb > bv[t] ||
                             (xb == bv[t] && id[xp] < id[bp[t]]));
                if (take) { bv[t] = xb; bp[t] = xp; }
            }
            __syncthreads();
        }
        if (t == 0) { g_topk[side][row * NN + k] = id[bp[0]]; v[bp[0]] = -1e38f; }
        __syncthreads();
    }
}

// ---------------- 5. gather neighbor columns (exact fp32) -----------------------
__global__ void gather_kernel(const float* __restrict__ qX,
                              const float* __restrict__ qY) {
    int j = blockIdx.x * 256 + threadIdx.x;
    int d = blockIdx.y;
    int side = blockIdx.z;
    const float* Q = side ? qX : qY;
    int c = g_topk[side][j];
    g_nnT[side][d * BN + j] = Q[(size_t)d * Rk + c];
}

// ---------------- 6. stage-2 logits GEMM + fixed-max partial LSE ----------------
#define FP 132
#define SM2_F 0
#define SM2_J (64 * FP)
#define SM2_S (SM2_J + 128 * 64)
#define SM2_P (SM2_S + 64)
#define SMEM2_BYTES ((SM2_P + 64) * 4)

__global__ void __launch_bounds__(256, 2) lse_gemm_kernel() {
    extern __shared__ float s2[];
    float* F = s2 + SM2_F;
    float* J = s2 + SM2_J;
    float* accS = s2 + SM2_S;
    float* accP = s2 + SM2_P;
    int t = threadIdx.x;
    int tx = t & 15, ty = t >> 4;
    int rg = blockIdx.x, jb = blockIdx.y, side = blockIdx.z;

    {
        const float* feat = g_feat[side] + rg * 64 * Dk;
        for (int i = t; i < 64 * Dk; i += 256) {
            int r = i >> 7, d = i & 127;
            F[r * FP + d] = feat[i];
        }
        if (t < 64) { accS[t] = 0.f; accP[t] = 0.f; }
    }
    __syncthreads();

    const float4* nn4 = reinterpret_cast<const float4*>(g_nnT[side]);
    for (int jt = 0; jt < JW / 64; ++jt) {
        float4* J4 = reinterpret_cast<float4*>(J);
        #pragma unroll
        for (int i = 0; i < 8; ++i) {
            int lin = i * 256 + t;
            int d = lin >> 4, c4 = lin & 15;
            J4[d * 16 + c4] = nn4[(size_t)d * (BN / 4) + jb * (JW / 4) + jt * 16 + c4];
        }
        __syncthreads();

        u64 acc[4][2];
        #pragma unroll
        for (int r = 0; r < 4; ++r) { acc[r][0] = 0ull; acc[r][1] = 0ull; }
        const float* fb = F + (ty * 4) * FP;
        #pragma unroll 8
        for (int d = 0; d < Dk; ++d) {
            ulonglong2 q = *reinterpret_cast<const ulonglong2*>(J + d * 64 + tx * 4);
            #pragma unroll
            for (int r = 0; r < 4; ++r) {
                u64 fd = dupf(fb[r * FP + d]);
                ffma2(acc[r][0], q.x, fd);
                ffma2(acc[r][1], q.y, fd);
            }
        }

        int j0 = jb * JW + jt * 64 + tx * 4;
        #pragma unroll
        for (int r = 0; r < 4; ++r) {
            float2 a = unpack2(acc[r][0]);
            float2 b2 = unpack2(acc[r][1]);
            float vv[4] = { a.x, a.y, b2.x, b2.y };
            int rowg = rg * 64 + ty * 4 + r;
            float sE = 0.f, sP = 0.f;
            #pragma unroll
            for (int i = 0; i < 4; ++i) {
                float lg = vv[i] * 10.f;            // / TEMP
                sE += __expf(lg - 10.f);            // fixed max = 10 (cos<=1)
                unsigned dj = (unsigned)(j0 + i - rowg * NN);
                if (dj < (unsigned)NN) sP += lg;
            }
            #pragma unroll
            for (int o = 8; o; o >>= 1) {
                sE += __shfl_xor_sync(0xFFFFFFFFu, sE, o);
                sP += __shfl_xor_sync(0xFFFFFFFFu, sP, o);
            }
            if (tx == 0) { accS[ty * 4 + r] += sE; accP[ty * 4 + r] += sP; }
        }
        __syncthreads();
    }
    if (t < 64) {
        int rowg = rg * 64 + t;
        g_pS[side][rowg][jb] = accS[t];
        g_pP[side][rowg][jb] = accP[t];
    }
}

// ---------------- 7. combine partials -> loss ------------------------------------
__global__ void combine_kernel(float* __restrict__ out) {
    __shared__ float red[1024];
    int t = threadIdx.x;
    float term = 0.f;
    #pragma unroll
    for (int side = 0; side < 2; ++side) {
        float S = 0.f, P = 0.f;
        #pragma unroll
        for (int jb = 0; jb < JBLK; ++jb) { S += g_pS[side][t][jb]; P += g_pP[side][t][jb]; }
        term += P - (float)NN * (10.f + logf(S));
    }
    red[t] = term;
    __syncthreads();
    for (int s = 512; s; s >>= 1) {
        if (t < s) red[t] += red[t + s];
        __syncthreads();
    }
    if (t == 0) out[0] = -red[0] / (float)Bk;
}

// ---------------- 8. queue head columns ------------------------------------------
__global__ void qhead_kernel(float* __restrict__ out) {
    int c = blockIdx.x * 256 + threadIdx.x;
    int d = blockIdx.y;
    int side = blockIdx.z;
    out[1 + (size_t)side * Dk * Rk + (size_t)d * Rk + c] = g_feat[side][c * Dk + d];
}

// ---------------- launch ----------------------------------------------------------
extern "C" void kernel_launch(void* const* d_in, const int* in_sizes, int n_in,
                              void* d_out, int out_size) {
    const float* fX = (const float*)d_in[0];
    const float* fY = (const float*)d_in[1];
    const float* qX = (const float*)d_in[2];
    const float* qY = (const float*)d_in[3];
    float* out = (float*)d_out;

    cudaFuncSetAttribute(simtopk_i8_kernel,
                         cudaFuncAttributeMaxDynamicSharedMemorySize, SMEM1);
    cudaFuncSetAttribute(lse_gemm_kernel,
                         cudaFuncAttributeMaxDynamicSharedMemorySize, SMEM2_BYTES);

    normalize_kernel<<<dim3(Bk, 2, 1), Dk>>>(fX, fY);
    colmax_kernel<<<dim3(Rk / 256, 2, 1), 256>>>(qX, qY);
    transposeQ_kernel<<<dim3(Rk / 32, Dk / 32, 2), dim3(32, 8, 1)>>>(qX, qY);

    simtopk_i8_kernel<<<dim3(NCH, 2, 1), 256, SMEM1>>>();
    topk_reduce_kernel<<<dim3(Bk, 2, 1), 256>>>();
    gather_kernel<<<dim3(BN / 256, Dk, 2), 256>>>(qX, qY);
    lse_gemm_kernel<<<dim3(Bk / 64, JBLK, 2), 256, SMEM2_BYTES>>>();
    combine_kernel<<<1, 1024>>>(out);

    cudaMemcpyAsync(out + 1, qX, (size_t)Dk * Rk * sizeof(float),
                    cudaMemcpyDeviceToDevice, 0);
    cudaMemcpyAsync(out + 1 + (size_t)Dk * Rk, qY, (size_t)Dk * Rk * sizeof(float),
                    cudaMemcpyDeviceToDevice, 0);
    qhead_kernel<<<dim3(Bk / 256, Dk, 2), 256>>>(out);
}

// round 5
// speedup vs baseline: 1.3081x; 1.1333x over previous
#include <cuda_runtime.h>
#include <cstdint>
#include <math.h>

#define Dk 128
#define Bk 1024
#define Rk 131072
#define NN 10
#define BN (Bk * NN)          // 10240
#define CHUNK 256             // cols per stage-1 CTA
#define NCH 512               // chunks
#define JBLK 16               // stage-2 j blocks
#define JW 640                // j per stage-2 block

typedef unsigned long long u64;
typedef unsigned int u32;
typedef unsigned short u16;

// ---------------- device scratch ----------------
__device__ float g_feat[2][Bk * Dk];          // normalized fp32 feats [row][d]
__device__ u32   g_featQ[2][32][Bk];          // int8 feats packed [kc][row]
__device__ u32   g_qQ[2][32][Rk];             // int8 queue packed [kc][r]
__device__ float g_qscale[2][Rk];             // per-column maxabs
__device__ float g_qmul[2][Rk];               // 127/maxabs
__device__ float g_candV[2][Bk * NCH * NN];   // sorted desc per (row,chunk)
__device__ int   g_candI[2][Bk * NCH * NN];
__device__ int   g_topk[2][Bk * NN];
__device__ float g_nnT[2][Dk * BN];           // gathered fp32 [d][j]
__device__ float g_pS[2][Bk][JBLK];
__device__ float g_pP[2][Bk][JBLK];

// ---------------- helpers ----------------
__device__ __forceinline__ void ffma2(u64 &d, u64 a, u64 b) {
    asm("fma.rn.f32x2 %0, %1, %2, %0;" : "+l"(d) : "l"(a), "l"(b));
}
__device__ __forceinline__ u64 dupf(float f) {
    u64 r; unsigned u = __float_as_uint(f);
    asm("mov.b64 %0, {%1, %2};" : "=l"(r) : "r"(u), "r"(u));
    return r;
}
__device__ __forceinline__ float2 unpack2(u64 a) {
    float2 o;
    asm("mov.b64 {%0, %1}, %2;" : "=f"(o.x), "=f"(o.y) : "l"(a));
    return o;
}

// ---------------- 1. normalize rows + int8 pack ---------------------------------
__global__ void normalize_kernel(const float* __restrict__ fX,
                                 const float* __restrict__ fY) {
    int side = blockIdx.y;
    int row = blockIdx.x;
    int d = threadIdx.x;
    const float* in = side ? fY : fX;
    float v = in[row * Dk + d];
    float sq = v * v;
    #pragma unroll
    for (int o = 16; o; o >>= 1) sq += __shfl_xor_sync(0xFFFFFFFFu, sq, o);
    __shared__ float ws[4], wm[4];
    __shared__ float nrm, smx;
    __shared__ unsigned char sb8[128];
    if ((d & 31) == 0) ws[d >> 5] = sq;
    __syncthreads();
    if (d == 0) nrm = sqrtf(ws[0] + ws[1] + ws[2] + ws[3]);
    __syncthreads();
    float nv = v / nrm;
    g_feat[side][row * Dk + d] = nv;
    float av = fabsf(nv);
    #pragma unroll
    for (int o = 16; o; o >>= 1) av = fmaxf(av, __shfl_xor_sync(0xFFFFFFFFu, av, o));
    if ((d & 31) == 0) wm[d >> 5] = av;
    __syncthreads();
    if (d == 0) smx = fmaxf(fmaxf(wm[0], wm[1]), fmaxf(wm[2], wm[3]));
    __syncthreads();
    int q = __float2int_rn(nv * (127.f / smx));
    sb8[d] = (unsigned char)(signed char)q;
    __syncthreads();
    if (d < 32) {
        u32 p = (u32)sb8[4 * d] | ((u32)sb8[4 * d + 1] << 8) |
                ((u32)sb8[4 * d + 2] << 16) | ((u32)sb8[4 * d + 3] << 24);
        g_featQ[side][d][row] = p;
    }
}

// ---------------- 2a. per-column maxabs of queue --------------------------------
__global__ void colmax_kernel(const float* __restrict__ qX,
                              const float* __restrict__ qY) {
    int side = blockIdx.y;
    const float* src = side ? qX : qY;   // side 0 (feat X) uses queue_Y
    int c = blockIdx.x * 256 + threadIdx.x;
    float mx = 1e-12f;
    for (int d = 0; d < Dk; ++d)
        mx = fmaxf(mx, fabsf(src[(size_t)d * Rk + c]));
    g_qscale[side][c] = mx;
    g_qmul[side][c] = 127.f / mx;
}

// ---------------- 2b. transpose + int8 quantize queue ---------------------------
__global__ void transposeQ_kernel(const float* __restrict__ qX,
                                  const float* __restrict__ qY) {
    int side = blockIdx.z;
    const float* src = side ? qX : qY;
    __shared__ float tile[32][33];
    int r0 = blockIdx.x * 32, d0 = blockIdx.y * 32;
    int tx = threadIdx.x, ty = threadIdx.y;
    #pragma unroll
    for (int i = 0; i < 4; ++i)
        tile[ty + i * 8][tx] = src[(size_t)(d0 + ty + i * 8) * Rk + r0 + tx];
    __syncthreads();
    float mul = g_qmul[side][r0 + tx];
    u32 p = 0;
    #pragma unroll
    for (int b = 0; b < 4; ++b) {
        int q = __float2int_rn(tile[ty * 4 + b][tx] * mul);
        p |= ((u32)(unsigned char)(signed char)q) << (8 * b);
    }
    g_qQ[side][(d0 >> 2) + ty][r0 + tx] = p;
}

// ---------------- 3. DP4A sim GEMM + fused per-chunk top-10 ---------------------
// CTA = one 256-col chunk, 16 M-tiles of 64 rows. 256 threads (16x16).
// Thread tile: 4 rows x 16 cols (4 col-groups at 64-col stride -> conflict-free).
#define S1_B  0                       // Qs u32 [kc][256] = 32768 B
#define S1_SC 32768                   // 256 floats       = 1024 B
#define S1_A  33792                   // As u32 [kc][64]  = 8192 B
#define S1_SS 41984                   // Ss [64][132] f32 = 33792 B
#define S1_CV 75776                   // 64*8*10 f32      = 20480 B
#define S1_CI 96256                   // 64*8*10 u16      = 10240 B
#define SMEM1 106496
#define SP1 132

__global__ void __launch_bounds__(256, 2) simtopk_i8_kernel() {
    extern __shared__ char sm[];
    u32*   Qs = reinterpret_cast<u32*>(sm + S1_B);
    float* SC = reinterpret_cast<float*>(sm + S1_SC);
    u32*   As = reinterpret_cast<u32*>(sm + S1_A);
    float* Ss = reinterpret_cast<float*>(sm + S1_SS);
    float* Cv = reinterpret_cast<float*>(sm + S1_CV);
    u16*   Ci = reinterpret_cast<u16*>(sm + S1_CI);
    int t = threadIdx.x, tx = t & 15, ty = t >> 4;
    int chunk = blockIdx.x, side = blockIdx.y;

    // load B chunk: 32 kc x 256 u32 (coalesced)
    for (int i = t; i < 2048; i += 256) {
        int kc = i >> 6, c4 = i & 63;
        reinterpret_cast<uint4*>(Qs + kc * 256)[c4] =
            reinterpret_cast<const uint4*>(&g_qQ[side][kc][chunk * CHUNK])[c4];
    }
    SC[t] = g_qscale[side][chunk * CHUNK + t];
    __syncthreads();

    for (int mt = 0; mt < 16; ++mt) {
        // load A tile: 32 kc x 64 rows u32
        for (int i = t; i < 512; i += 256) {
            int kc = i >> 4, r4 = i & 15;
            reinterpret_cast<uint4*>(As + kc * 64)[r4] =
                reinterpret_cast<const uint4*>(&g_featQ[side][kc][mt * 64])[r4];
        }
        __syncthreads();

        int acc[4][16];
        #pragma unroll
        for (int r = 0; r < 4; ++r)
            #pragma unroll
            for (int c = 0; c < 16; ++c) acc[r][c] = 0;

        #pragma unroll 4
        for (int kc = 0; kc < 32; ++kc) {
            int f[4];
            #pragma unroll
            for (int r = 0; r < 4; ++r) f[r] = (int)As[kc * 64 + ty * 4 + r];
            const u32* qrow = Qs + kc * 256 + tx * 4;
            #pragma unroll
            for (int g = 0; g < 4; ++g) {
                uint4 qa = *reinterpret_cast<const uint4*>(qrow + g * 64);
                #pragma unroll
                for (int r = 0; r < 4; ++r) {
                    acc[r][g * 4 + 0] = __dp4a((int)qa.x, f[r], acc[r][g * 4 + 0]);
                    acc[r][g * 4 + 1] = __dp4a((int)qa.y, f[r], acc[r][g * 4 + 1]);
                    acc[r][g * 4 + 2] = __dp4a((int)qa.z, f[r], acc[r][g * 4 + 2]);
                    acc[r][g * 4 + 3] = __dp4a((int)qa.w, f[r], acc[r][g * 4 + 3]);
                }
            }
        }

        // epilogue: two 128-col halves through Ss
        #pragma unroll
        for (int h = 0; h < 2; ++h) {
            #pragma unroll
            for (int g = 2 * h; g < 2 * h + 2; ++g) {
                float4 s = *reinterpret_cast<const float4*>(SC + g * 64 + tx * 4);
                int lc = (g & 1) * 64 + tx * 4;
                #pragma unroll
                for (int r = 0; r < 4; ++r) {
                    float4 w = make_float4((float)acc[r][g * 4 + 0] * s.x,
                                           (float)acc[r][g * 4 + 1] * s.y,
                                           (float)acc[r][g * 4 + 2] * s.z,
                                           (float)acc[r][g * 4 + 3] * s.w);
                    *reinterpret_cast<float4*>(Ss + (ty * 4 + r) * SP1 + lc) = w;
                }
            }
            __syncthreads();

            // scan: 64 rows x 4 segs, each thread 32 cols of this half
            {
                int row = t >> 2, seg = t & 3;
                float* cv = Cv + (row * 8 + h * 4 + seg) * NN;
                u16*   ci = Ci + (row * 8 + h * 4 + seg) * NN;
                #pragma unroll
                for (int k = 0; k < NN; ++k) { cv[k] = -1e30f; ci[k] = 0xffff; }
                float tv9 = -1e30f;
                const float* sp = Ss + row * SP1;
                for (int i = 0; i < 32; ++i) {
                    int lcol = seg + 4 * i;
                    float v = sp[lcol];
                    if (v > tv9) {
                        int p = NN - 1;
                        while (p > 0 && cv[p - 1] < v) {
                            cv[p] = cv[p - 1]; ci[p] = ci[p - 1]; --p;
                        }
                        cv[p] = v; ci[p] = (u16)(h * 128 + lcol);
                        tv9 = cv[NN - 1];
                    }
                }
            }
            __syncthreads();
        }

        // merge 8 sorted lists -> top-10 per row (Ss reused as scratch)
        if (t < 64) {
            float* mv = Ss + t * 16;
            int*   mi = reinterpret_cast<int*>(Ss + 1024 + t * 16);
            #pragma unroll
            for (int k = 0; k < NN; ++k) { mv[k] = -1e30f; mi[k] = 0x7fffffff; }
            float tv9 = -1e30f; int ti9 = 0x7fffffff;
            for (int s = 0; s < 8; ++s) {
                const float* cv = Cv + (t * 8 + s) * NN;
                const u16*   ci = Ci + (t * 8 + s) * NN;
                for (int k = 0; k < NN; ++k) {
                    float v = cv[k];
                    if (v < tv9) break;
                    int id = (int)ci[k];
                    if (v == tv9 && id >= ti9) continue;
                    int p = NN - 1;
                    while (p > 0 && (mv[p - 1] < v ||
                                     (mv[p - 1] == v && mi[p - 1] > id))) {
                        mv[p] = mv[p - 1]; mi[p] = mi[p - 1]; --p;
                    }
                    mv[p] = v; mi[p] = id;
                    tv9 = mv[NN - 1]; ti9 = mi[NN - 1];
                }
            }
            size_t gb = ((size_t)(mt * 64 + t) * NCH + chunk) * NN;
            #pragma unroll
            for (int k = 0; k < NN; ++k) {
                g_candV[side][gb + k] = mv[k];
                g_candI[side][gb + k] = chunk * CHUNK + mi[k];
            }
        }
        __syncthreads();
    }
}

// ---------------- 4. heads-merge of 512 sorted lists -> top-10 per row ----------
__global__ void topk_reduce_kernel() {
    __shared__ float hv[NCH];
    __shared__ int   hi[NCH];
    __shared__ unsigned char hp[NCH];
    __shared__ float bv[256];
    __shared__ int   bp[256];
    int row = blockIdx.x;
    int side = blockIdx.y;
    int t = threadIdx.x;
    const float* CV = &g_candV[side][(size_t)row * (NCH * NN)];
    const int*   CI = &g_candI[side][(size_t)row * (NCH * NN)];
    for (int c = t; c < NCH; c += 256) {
        hv[c] = CV[c * NN]; hi[c] = CI[c * NN]; hp[c] = 0;
    }
    __syncthreads();
    for (int k = 0; k < NN; ++k) {
        float v1 = hv[t], v2 = hv[t + 256];
        int c1 = t, c2 = t + 256;
        bool take2 = (v2 > v1) || (v2 == v1 && hi[c2] < hi[c1]);
        bv[t] = take2 ? v2 : v1;
        bp[t] = take2 ? c2 : c1;
        __syncthreads();
        for (int s = 128; s; s >>= 1) {
            if (t < s) {
                float xb = bv[t + s]; int xc = bp[t + s];
                if (xb > bv[t] || (xb == bv[t] && hi[xc] < hi[bp[t]])) {
                    bv[t] = xb; bp[t] = xc;
                }
            }
            __syncthreads();
        }
        if (t == 0) {
            int c = bp[0];
            g_topk[side][row * NN + k] = hi[c];
            int p = (int)(++hp[c]);
            if (p < NN) { hv[c] = CV[c * NN + p]; hi[c] = CI[c * NN + p]; }
            else        { hv[c] = -1e38f;         hi[c] = 0x7fffffff; }
        }
        __syncthreads();
    }
}

// ---------------- 5. gather neighbor columns (exact fp32) -----------------------
__global__ void gather_kernel(const float* __restrict__ qX,
                              const float* __restrict__ qY) {
    int j = blockIdx.x * 256 + threadIdx.x;
    int d = blockIdx.y;
    int side = blockIdx.z;
    const float* Q = side ? qX : qY;
    int c = g_topk[side][j];
    g_nnT[side][d * BN + j] = Q[(size_t)d * Rk + c];
}

// ---------------- 6. stage-2 logits GEMM + fixed-max partial LSE ----------------
#define FP 132
#define SM2_F 0
#define SM2_J (64 * FP)
#define SM2_S (SM2_J + 128 * 64)
#define SM2_P (SM2_S + 64)
#define SMEM2_BYTES ((SM2_P + 64) * 4)

__global__ void __launch_bounds__(256, 3) lse_gemm_kernel() {
    extern __shared__ float s2[];
    float* F = s2 + SM2_F;
    float* J = s2 + SM2_J;
    float* accS = s2 + SM2_S;
    float* accP = s2 + SM2_P;
    int t = threadIdx.x;
    int tx = t & 15, ty = t >> 4;
    int rg = blockIdx.x, jb = blockIdx.y, side = blockIdx.z;

    {
        const float* feat = g_feat[side] + rg * 64 * Dk;
        for (int i = t; i < 64 * Dk; i += 256) {
            int r = i >> 7, d = i & 127;
            F[r * FP + d] = feat[i];
        }
        if (t < 64) { accS[t] = 0.f; accP[t] = 0.f; }
    }
    __syncthreads();

    const float4* nn4 = reinterpret_cast<const float4*>(g_nnT[side]);
    for (int jt = 0; jt < JW / 64; ++jt) {
        float4* J4 = reinterpret_cast<float4*>(J);
        #pragma unroll
        for (int i = 0; i < 8; ++i) {
            int lin = i * 256 + t;
            int d = lin >> 4, c4 = lin & 15;
            J4[d * 16 + c4] = nn4[(size_t)d * (BN / 4) + jb * (JW / 4) + jt * 16 + c4];
        }
        __syncthreads();

        u64 acc[4][2];
        #pragma unroll
        for (int r = 0; r < 4; ++r) { acc[r][0] = 0ull; acc[r][1] = 0ull; }
        const float* fb = F + (ty * 4) * FP;
        #pragma unroll 8
        for (int d = 0; d < Dk; ++d) {
            ulonglong2 q = *reinterpret_cast<const ulonglong2*>(J + d * 64 + tx * 4);
            #pragma unroll
            for (int r = 0; r < 4; ++r) {
                u64 fd = dupf(fb[r * FP + d]);
                ffma2(acc[r][0], q.x, fd);
                ffma2(acc[r][1], q.y, fd);
            }
        }

        int j0 = jb * JW + jt * 64 + tx * 4;
        #pragma unroll
        for (int r = 0; r < 4; ++r) {
            float2 a = unpack2(acc[r][0]);
            float2 b2 = unpack2(acc[r][1]);
            float vv[4] = { a.x, a.y, b2.x, b2.y };
            int rowg = rg * 64 + ty * 4 + r;
            float sE = 0.f, sP = 0.f;
            #pragma unroll
            for (int i = 0; i < 4; ++i) {
                float lg = vv[i] * 10.f;            // / TEMP
                sE += __expf(lg - 10.f);            // fixed max = 10 (cos<=1)
                unsigned dj = (unsigned)(j0 + i - rowg * NN);
                if (dj < (unsigned)NN) sP += lg;
            }
            #pragma unroll
            for (int o = 8; o; o >>= 1) {
                sE += __shfl_xor_sync(0xFFFFFFFFu, sE, o);
                sP += __shfl_xor_sync(0xFFFFFFFFu, sP, o);
            }
            if (tx == 0) { accS[ty * 4 + r] += sE; accP[ty * 4 + r] += sP; }
        }
        __syncthreads();
    }
    if (t < 64) {
        int rowg = rg * 64 + t;
        g_pS[side][rowg][jb] = accS[t];
        g_pP[side][rowg][jb] = accP[t];
    }
}

// ---------------- 7. combine partials -> loss ------------------------------------
__global__ void combine_kernel(float* __restrict__ out) {
    __shared__ float red[1024];
    int t = threadIdx.x;
    float term = 0.f;
    #pragma unroll
    for (int side = 0; side < 2; ++side) {
        float S = 0.f, P = 0.f;
        #pragma unroll
        for (int jb = 0; jb < JBLK; ++jb) { S += g_pS[side][t][jb]; P += g_pP[side][t][jb]; }
        term += P - (float)NN * (10.f + logf(S));
    }
    red[t] = term;
    __syncthreads();
    for (int s = 512; s; s >>= 1) {
        if (t < s) red[t] += red[t + s];
        __syncthreads();
    }
    if (t == 0) out[0] = -red[0] / (float)Bk;
}

// ---------------- 8. queue head columns ------------------------------------------
__global__ void qhead_kernel(float* __restrict__ out) {
    int c = blockIdx.x * 256 + threadIdx.x;
    int d = blockIdx.y;
    int side = blockIdx.z;
    out[1 + (size_t)side * Dk * Rk + (size_t)d * Rk + c] = g_feat[side][c * Dk + d];
}

// ---------------- launch ----------------------------------------------------------
extern "C" void kernel_launch(void* const* d_in, const int* in_sizes, int n_in,
                              void* d_out, int out_size) {
    const float* fX = (const float*)d_in[0];
    const float* fY = (const float*)d_in[1];
    const float* qX = (const float*)d_in[2];
    const float* qY = (const float*)d_in[3];
    float* out = (float*)d_out;

    cudaFuncSetAttribute(simtopk_i8_kernel,
                         cudaFuncAttributeMaxDynamicSharedMemorySize, SMEM1);
    cudaFuncSetAttribute(lse_gemm_kernel,
                         cudaFuncAttributeMaxDynamicSharedMemorySize, SMEM2_BYTES);

    normalize_kernel<<<dim3(Bk, 2, 1), Dk>>>(fX, fY);
    colmax_kernel<<<dim3(Rk / 256, 2, 1), 256>>>(qX, qY);
    transposeQ_kernel<<<dim3(Rk / 32, Dk / 32, 2), dim3(32, 8, 1)>>>(qX, qY);

    simtopk_i8_kernel<<<dim3(NCH, 2, 1), 256, SMEM1>>>();
    topk_reduce_kernel<<<dim3(Bk, 2, 1), 256>>>();
    gather_kernel<<<dim3(BN / 256, Dk, 2), 256>>>(qX, qY);
    lse_gemm_kernel<<<dim3(Bk / 64, JBLK, 2), 256, SMEM2_BYTES>>>();
    combine_kernel<<<1, 1024>>>(out);

    cudaMemcpyAsync(out + 1, qX, (size_t)Dk * Rk * sizeof(float),
                    cudaMemcpyDeviceToDevice, 0);
    cudaMemcpyAsync(out + 1 + (size_t)Dk * Rk, qY, (size_t)Dk * Rk * sizeof(float),
                    cudaMemcpyDeviceToDevice, 0);
    qhead_kernel<<<dim3(Bk / 256, Dk, 2), 256>>>(out);
}

// round 6
// speedup vs baseline: 4.7988x; 3.6686x over previous
#include <cuda_runtime.h>
#include <cstdint>
#include <math.h>

#define Dk 128
#define Bk 1024
#define Rk 131072
#define NN 10
#define BN (Bk * NN)          // 10240
#define RNG 8                 // column ranges (stage-1 grid.x)
#define RSPAN (Rk / RNG)      // 16384 cols per CTA
#define SUB 128               // cols per sub-chunk
#define NSUB (RSPAN / SUB)    // 128
#define JBLK 16               // stage-2 j blocks
#define JW 640                // j per stage-2 block

typedef unsigned long long u64;
typedef unsigned int u32;
typedef unsigned short u16;

// ---------------- device scratch ----------------
__device__ float g_feat[2][Bk * Dk];          // normalized fp32 feats [row][d]
__device__ u32   g_featQ[2][32][Bk];          // int8 feats packed [kc][row]
__device__ u32   g_qQ[2][32][Rk];             // int8 queue packed [kc][r]
__device__ float g_qscale[2][Rk];             // per-column maxabs
__device__ float g_qmul[2][Rk];               // 127/maxabs
__device__ float g_candV[2][Bk * RNG * NN];   // sorted desc per (row,range)
__device__ int   g_candI[2][Bk * RNG * NN];
__device__ int   g_topk[2][Bk * NN];
__device__ float g_nnT[2][Dk * BN];           // gathered fp32 [d][j]
__device__ float g_pS[2][Bk][JBLK];
__device__ float g_pP[2][Bk][JBLK];

// ---------------- helpers ----------------
__device__ __forceinline__ void ffma2(u64 &d, u64 a, u64 b) {
    asm("fma.rn.f32x2 %0, %1, %2, %0;" : "+l"(d) : "l"(a), "l"(b));
}
__device__ __forceinline__ u64 dupf(float f) {
    u64 r; unsigned u = __float_as_uint(f);
    asm("mov.b64 %0, {%1, %2};" : "=l"(r) : "r"(u), "r"(u));
    return r;
}
__device__ __forceinline__ float2 unpack2(u64 a) {
    float2 o;
    asm("mov.b64 {%0, %1}, %2;" : "=f"(o.x), "=f"(o.y) : "l"(a));
    return o;
}

// ---------------- 1. normalize rows + int8 pack ---------------------------------
__global__ void normalize_kernel(const float* __restrict__ fX,
                                 const float* __restrict__ fY) {
    int side = blockIdx.y;
    int row = blockIdx.x;
    int d = threadIdx.x;
    const float* in = side ? fY : fX;
    float v = in[row * Dk + d];
    float sq = v * v;
    #pragma unroll
    for (int o = 16; o; o >>= 1) sq += __shfl_xor_sync(0xFFFFFFFFu, sq, o);
    __shared__ float ws[4], wm[4];
    __shared__ float nrm, smx;
    __shared__ unsigned char sb8[128];
    if ((d & 31) == 0) ws[d >> 5] = sq;
    __syncthreads();
    if (d == 0) nrm = sqrtf(ws[0] + ws[1] + ws[2] + ws[3]);
    __syncthreads();
    float nv = v / nrm;
    g_feat[side][row * Dk + d] = nv;
    float av = fabsf(nv);
    #pragma unroll
    for (int o = 16; o; o >>= 1) av = fmaxf(av, __shfl_xor_sync(0xFFFFFFFFu, av, o));
    if ((d & 31) == 0) wm[d >> 5] = av;
    __syncthreads();
    if (d == 0) smx = fmaxf(fmaxf(wm[0], wm[1]), fmaxf(wm[2], wm[3]));
    __syncthreads();
    int q = __float2int_rn(nv * (127.f / smx));
    sb8[d] = (unsigned char)(signed char)q;
    __syncthreads();
    if (d < 32) {
        u32 p = (u32)sb8[4 * d] | ((u32)sb8[4 * d + 1] << 8) |
                ((u32)sb8[4 * d + 2] << 16) | ((u32)sb8[4 * d + 3] << 24);
        g_featQ[side][d][row] = p;
    }
}

// ---------------- 2a. per-column maxabs of queue --------------------------------
__global__ void colmax_kernel(const float* __restrict__ qX,
                              const float* __restrict__ qY) {
    int side = blockIdx.y;
    const float* src = side ? qX : qY;   // side 0 (feat X) uses queue_Y
    int c = blockIdx.x * 256 + threadIdx.x;
    float mx = 1e-12f;
    for (int d = 0; d < Dk; ++d)
        mx = fmaxf(mx, fabsf(src[(size_t)d * Rk + c]));
    g_qscale[side][c] = mx;
    g_qmul[side][c] = 127.f / mx;
}

// ---------------- 2b. transpose + int8 quantize queue ---------------------------
__global__ void transposeQ_kernel(const float* __restrict__ qX,
                                  const float* __restrict__ qY) {
    int side = blockIdx.z;
    const float* src = side ? qX : qY;
    __shared__ float tile[32][33];
    int r0 = blockIdx.x * 32, d0 = blockIdx.y * 32;
    int tx = threadIdx.x, ty = threadIdx.y;
    #pragma unroll
    for (int i = 0; i < 4; ++i)
        tile[ty + i * 8][tx] = src[(size_t)(d0 + ty + i * 8) * Rk + r0 + tx];
    __syncthreads();
    float mul = g_qmul[side][r0 + tx];
    u32 p = 0;
    #pragma unroll
    for (int b = 0; b < 4; ++b) {
        int q = __float2int_rn(tile[ty * 4 + b][tx] * mul);
        p |= ((u32)(unsigned char)(signed char)q) << (8 * b);
    }
    g_qQ[side][(d0 >> 2) + ty][r0 + tx] = p;
}

// ---------------- 3. DP4A sim GEMM + persistent per-row top-10 ------------------
// CTA = 64 rows x 16384-col range. 256 threads (16x16), loop 128 sub-chunks of 128.
// Top-10 lists (64 rows x 4 segs) PERSIST across the whole range -> rare inserts.
#define S_QS 0                        // Qs u32 [kc][128]  = 16384 B
#define S_SC 16384                    // 128 f             = 512 B
#define S_AS 16896                    // As u32 [kc][64]   = 8192 B
#define S_SS 25088                    // Ss [64][132] f    = 33792 B
#define S_CV 58880                    // 256*11 f          = 11264 B
#define S_CI 70144                    // 256*11 u16        = 5632 B
#define SMEM1 75776
#define SP1 132
#define LP 11

__global__ void __launch_bounds__(256, 2) simtopk_i8_kernel() {
    extern __shared__ char sm[];
    u32*   Qs = reinterpret_cast<u32*>(sm + S_QS);
    float* SC = reinterpret_cast<float*>(sm + S_SC);
    u32*   As = reinterpret_cast<u32*>(sm + S_AS);
    float* Ss = reinterpret_cast<float*>(sm + S_SS);
    float* Cv = reinterpret_cast<float*>(sm + S_CV);
    u16*   Ci = reinterpret_cast<u16*>(sm + S_CI);
    int t = threadIdx.x, tx = t & 15, ty = t >> 4;
    int range = blockIdx.x, rt = blockIdx.y, side = blockIdx.z;
    int colBase = range * RSPAN;

    // A tile once: 32 kc x 64 rows
    for (int i = t; i < 512; i += 256) {
        int kc = i >> 4, r4 = i & 15;
        reinterpret_cast<uint4*>(As + kc * 64)[r4] =
            reinterpret_cast<const uint4*>(&g_featQ[side][kc][rt * 64])[r4];
    }
    // init persistent lists (one per thread)
    #pragma unroll
    for (int k = 0; k < NN; ++k) { Cv[t * LP + k] = -1e30f; Ci[t * LP + k] = 0xffff; }
    float tv9 = -1e30f;

    // first Qs/SC tile
    {
        const uint4* qsrc = reinterpret_cast<const uint4*>(&g_qQ[side][0][0]);
        #pragma unroll
        for (int j = 0; j < 4; ++j) {
            int lin = t * 4 + j;
            int kc = lin >> 5, c4 = lin & 31;
            reinterpret_cast<uint4*>(Qs + kc * 128)[c4] =
                qsrc[(size_t)kc * (Rk / 4) + (colBase >> 2) + c4];
        }
        if (t < 32)
            reinterpret_cast<float4*>(SC)[t] =
                reinterpret_cast<const float4*>(&g_qscale[side][colBase])[t];
    }
    __syncthreads();

    int row = t >> 2, seg = t & 3;
    float* myCv = Cv + t * LP;
    u16*   myCi = Ci + t * LP;

    for (int sc = 0; sc < NSUB; ++sc) {
        // prefetch next tile into registers (in flight during mainloop)
        uint4 nq[4]; float4 nsc;
        bool have = (sc + 1 < NSUB);
        if (have) {
            const uint4* qsrc = reinterpret_cast<const uint4*>(&g_qQ[side][0][0]);
            int cb4 = (colBase + (sc + 1) * SUB) >> 2;
            #pragma unroll
            for (int j = 0; j < 4; ++j) {
                int lin = t * 4 + j;
                int kc = lin >> 5, c4 = lin & 31;
                nq[j] = qsrc[(size_t)kc * (Rk / 4) + cb4 + c4];
            }
            if (t < 32)
                nsc = reinterpret_cast<const float4*>(
                          &g_qscale[side][colBase + (sc + 1) * SUB])[t];
        }

        // mainloop: 4 rows x 8 cols per thread
        int acc[4][8];
        #pragma unroll
        for (int r = 0; r < 4; ++r)
            #pragma unroll
            for (int c = 0; c < 8; ++c) acc[r][c] = 0;
        #pragma unroll 4
        for (int kc = 0; kc < 32; ++kc) {
            int f[4];
            #pragma unroll
            for (int r = 0; r < 4; ++r) f[r] = (int)As[kc * 64 + ty * 4 + r];
            #pragma unroll
            for (int g = 0; g < 2; ++g) {
                uint4 q = *reinterpret_cast<const uint4*>(Qs + kc * 128 + g * 64 + tx * 4);
                #pragma unroll
                for (int r = 0; r < 4; ++r) {
                    acc[r][g * 4 + 0] = __dp4a((int)q.x, f[r], acc[r][g * 4 + 0]);
                    acc[r][g * 4 + 1] = __dp4a((int)q.y, f[r], acc[r][g * 4 + 1]);
                    acc[r][g * 4 + 2] = __dp4a((int)q.z, f[r], acc[r][g * 4 + 2]);
                    acc[r][g * 4 + 3] = __dp4a((int)q.w, f[r], acc[r][g * 4 + 3]);
                }
            }
        }

        // scaled sims to Ss
        #pragma unroll
        for (int g = 0; g < 2; ++g) {
            float4 s = *reinterpret_cast<const float4*>(SC + g * 64 + tx * 4);
            #pragma unroll
            for (int r = 0; r < 4; ++r) {
                float4 w = make_float4((float)acc[r][g * 4 + 0] * s.x,
                                       (float)acc[r][g * 4 + 1] * s.y,
                                       (float)acc[r][g * 4 + 2] * s.z,
                                       (float)acc[r][g * 4 + 3] * s.w);
                *reinterpret_cast<float4*>(Ss + (ty * 4 + r) * SP1 + g * 64 + tx * 4) = w;
            }
        }
        __syncthreads();   // Qs reads + Ss writes done

        // store prefetched tile (scan does not touch Qs/SC)
        if (have) {
            #pragma unroll
            for (int j = 0; j < 4; ++j) {
                int lin = t * 4 + j;
                int kc = lin >> 5, c4 = lin & 31;
                reinterpret_cast<uint4*>(Qs + kc * 128)[c4] = nq[j];
            }
            if (t < 32) reinterpret_cast<float4*>(SC)[t] = nsc;
        }

        // scan: thread owns (row, seg), cols seg+4i, persistent list
        {
            const float* sp = Ss + row * SP1;
            u16 ib = (u16)(sc * SUB);
            #pragma unroll 4
            for (int i = 0; i < 32; ++i) {
                int col = seg + 4 * i;
                float v = sp[col];
                if (v > tv9) {
                    int p = NN - 1;
                    while (p > 0 && myCv[p - 1] < v) {
                        myCv[p] = myCv[p - 1]; myCi[p] = myCi[p - 1]; --p;
                    }
                    myCv[p] = v; myCi[p] = (u16)(ib + col);
                    tv9 = myCv[NN - 1];
                }
            }
        }
        __syncthreads();   // Ss reads done; Qs refilled
    }

    // merge 4 seg-lists per row -> sorted top-10 -> g_cand
    if (t < 64) {
        float* mv = Ss + t * 16;
        int*   mi = reinterpret_cast<int*>(Ss + 1024 + t * 16);
        #pragma unroll
        for (int k = 0; k < NN; ++k) { mv[k] = -1e30f; mi[k] = 0x7fffffff; }
        float m9 = -1e30f; int i9 = 0x7fffffff;
        for (int s = 0; s < 4; ++s) {
            const float* cv = Cv + (t * 4 + s) * LP;
            const u16*   ci = Ci + (t * 4 + s) * LP;
            for (int k = 0; k < NN; ++k) {
                float v = cv[k];
                if (v < m9) break;
                int id = (int)ci[k];
                if (v == m9 && id >= i9) continue;
                int p = NN - 1;
                while (p > 0 && (mv[p - 1] < v ||
                                 (mv[p - 1] == v && mi[p - 1] > id))) {
                    mv[p] = mv[p - 1]; mi[p] = mi[p - 1]; --p;
                }
                mv[p] = v; mi[p] = id;
                m9 = mv[NN - 1]; i9 = mi[NN - 1];
            }
        }
        size_t gb = (((size_t)(rt * 64 + t) * RNG) + range) * NN;
        #pragma unroll
        for (int k = 0; k < NN; ++k) {
            g_candV[side][gb + k] = mv[k];
            g_candI[side][gb + k] = colBase + mi[k];
        }
    }
}

// ---------------- 4. per-row 8-way heads merge -> final top-10 ------------------
__global__ void topk_merge_kernel() {
    __shared__ float cv[64 * 80];
    __shared__ int   ci[64 * 80];
    int b = blockIdx.x, side = blockIdx.y, t = threadIdx.x;  // 64 threads
    int row0 = b * 64;
    for (int i = t; i < 64 * 80; i += 64) {
        cv[i] = g_candV[side][(size_t)row0 * 80 + i];
        ci[i] = g_candI[side][(size_t)row0 * 80 + i];
    }
    __syncthreads();
    const float* v = cv + t * 80;
    const int*   id = ci + t * 80;
    int cur[8];
    #pragma unroll
    for (int h = 0; h < 8; ++h) cur[h] = h * 10;
    for (int k = 0; k < NN; ++k) {
        float best = -1e38f; int bi = 0x7fffffff; int bh = 0;
        #pragma unroll
        for (int h = 0; h < 8; ++h) {
            int c = cur[h];
            if (c < h * 10 + 10) {
                float x = v[c];
                int xi = id[c];
                if (x > best || (x == best && xi < bi)) { best = x; bi = xi; bh = h; }
            }
        }
        g_topk[side][(row0 + t) * NN + k] = bi;
        #pragma unroll
        for (int h = 0; h < 8; ++h) cur[h] += (h == bh);
    }
}

// ---------------- 5. gather neighbor columns (exact fp32) -----------------------
__global__ void gather_kernel(const float* __restrict__ qX,
                              const float* __restrict__ qY) {
    int j = blockIdx.x * 256 + threadIdx.x;
    int d = blockIdx.y;
    int side = blockIdx.z;
    const float* Q = side ? qX : qY;
    int c = g_topk[side][j];
    g_nnT[side][d * BN + j] = Q[(size_t)d * Rk + c];
}

// ---------------- 6. stage-2 logits GEMM + fixed-max partial LSE ----------------
#define FP 132
#define SM2_F 0
#define SM2_J (64 * FP)
#define SM2_S (SM2_J + 128 * 64)
#define SM2_P (SM2_S + 64)
#define SMEM2_BYTES ((SM2_P + 64) * 4)

__global__ void __launch_bounds__(256, 3) lse_gemm_kernel() {
    extern __shared__ float s2[];
    float* F = s2 + SM2_F;
    float* J = s2 + SM2_J;
    float* accS = s2 + SM2_S;
    float* accP = s2 + SM2_P;
    int t = threadIdx.x;
    int tx = t & 15, ty = t >> 4;
    int rg = blockIdx.x, jb = blockIdx.y, side = blockIdx.z;

    {
        const float* feat = g_feat[side] + rg * 64 * Dk;
        for (int i = t; i < 64 * Dk; i += 256) {
            int r = i >> 7, d = i & 127;
            F[r * FP + d] = feat[i];
        }
        if (t < 64) { accS[t] = 0.f; accP[t] = 0.f; }
    }
    __syncthreads();

    const float4* nn4 = reinterpret_cast<const float4*>(g_nnT[side]);
    for (int jt = 0; jt < JW / 64; ++jt) {
        float4* J4 = reinterpret_cast<float4*>(J);
        #pragma unroll
        for (int i = 0; i < 8; ++i) {
            int lin = i * 256 + t;
            int d = lin >> 4, c4 = lin & 15;
            J4[d * 16 + c4] = nn4[(size_t)d * (BN / 4) + jb * (JW / 4) + jt * 16 + c4];
        }
        __syncthreads();

        u64 acc[4][2];
        #pragma unroll
        for (int r = 0; r < 4; ++r) { acc[r][0] = 0ull; acc[r][1] = 0ull; }
        const float* fb = F + (ty * 4) * FP;
        #pragma unroll 8
        for (int d = 0; d < Dk; ++d) {
            ulonglong2 q = *reinterpret_cast<const ulonglong2*>(J + d * 64 + tx * 4);
            #pragma unroll
            for (int r = 0; r < 4; ++r) {
                u64 fd = dupf(fb[r * FP + d]);
                ffma2(acc[r][0], q.x, fd);
                ffma2(acc[r][1], q.y, fd);
            }
        }

        int j0 = jb * JW + jt * 64 + tx * 4;
        #pragma unroll
        for (int r = 0; r < 4; ++r) {
            float2 a = unpack2(acc[r][0]);
            float2 b2 = unpack2(acc[r][1]);
            float vv[4] = { a.x, a.y, b2.x, b2.y };
            int rowg = rg * 64 + ty * 4 + r;
            float sE = 0.f, sP = 0.f;
            #pragma unroll
            for (int i = 0; i < 4; ++i) {
                float lg = vv[i] * 10.f;            // / TEMP
                sE += __expf(lg - 10.f);            // fixed max = 10 (cos<=1)
                unsigned dj = (unsigned)(j0 + i - rowg * NN);
                if (dj < (unsigned)NN) sP += lg;
            }
            #pragma unroll
            for (int o = 8; o; o >>= 1) {
                sE += __shfl_xor_sync(0xFFFFFFFFu, sE, o);
                sP += __shfl_xor_sync(0xFFFFFFFFu, sP, o);
            }
            if (tx == 0) { accS[ty * 4 + r] += sE; accP[ty * 4 + r] += sP; }
        }
        __syncthreads();
    }
    if (t < 64) {
        int rowg = rg * 64 + t;
        g_pS[side][rowg][jb] = accS[t];
        g_pP[side][rowg][jb] = accP[t];
    }
}

// ---------------- 7. combine partials -> loss ------------------------------------
__global__ void combine_kernel(float* __restrict__ out) {
    __shared__ float red[1024];
    int t = threadIdx.x;
    float term = 0.f;
    #pragma unroll
    for (int side = 0; side < 2; ++side) {
        float S = 0.f, P = 0.f;
        #pragma unroll
        for (int jb = 0; jb < JBLK; ++jb) { S += g_pS[side][t][jb]; P += g_pP[side][t][jb]; }
        term += P - (float)NN * (10.f + logf(S));
    }
    red[t] = term;
    __syncthreads();
    for (int s = 512; s; s >>= 1) {
        if (t < s) red[t] += red[t + s];
        __syncthreads();
    }
    if (t == 0) out[0] = -red[0] / (float)Bk;
}

// ---------------- 8. queue head columns ------------------------------------------
__global__ void qhead_kernel(float* __restrict__ out) {
    int c = blockIdx.x * 256 + threadIdx.x;
    int d = blockIdx.y;
    int side = blockIdx.z;
    out[1 + (size_t)side * Dk * Rk + (size_t)d * Rk + c] = g_feat[side][c * Dk + d];
}

// ---------------- launch ----------------------------------------------------------
extern "C" void kernel_launch(void* const* d_in, const int* in_sizes, int n_in,
                              void* d_out, int out_size) {
    const float* fX = (const float*)d_in[0];
    const float* fY = (const float*)d_in[1];
    const float* qX = (const float*)d_in[2];
    const float* qY = (const float*)d_in[3];
    float* out = (float*)d_out;

    cudaFuncSetAttribute(simtopk_i8_kernel,
                         cudaFuncAttributeMaxDynamicSharedMemorySize, SMEM1);
    cudaFuncSetAttribute(lse_gemm_kernel,
                         cudaFuncAttributeMaxDynamicSharedMemorySize, SMEM2_BYTES);

    normalize_kernel<<<dim3(Bk, 2, 1), Dk>>>(fX, fY);
    colmax_kernel<<<dim3(Rk / 256, 2, 1), 256>>>(qX, qY);
    transposeQ_kernel<<<dim3(Rk / 32, Dk / 32, 2), dim3(32, 8, 1)>>>(qX, qY);

    simtopk_i8_kernel<<<dim3(RNG, Bk / 64, 2), 256, SMEM1>>>();
    topk_merge_kernel<<<dim3(Bk / 64, 2, 1), 64>>>();
    gather_kernel<<<dim3(BN / 256, Dk, 2), 256>>>(qX, qY);
    lse_gemm_kernel<<<dim3(Bk / 64, JBLK, 2), 256, SMEM2_BYTES>>>();
    combine_kernel<<<1, 1024>>>(out);

    cudaMemcpyAsync(out + 1, qX, (size_t)Dk * Rk * sizeof(float),
                    cudaMemcpyDeviceToDevice, 0);
    cudaMemcpyAsync(out + 1 + (size_t)Dk * Rk, qY, (size_t)Dk * Rk * sizeof(float),
                    cudaMemcpyDeviceToDevice, 0);
    qhead_kernel<<<dim3(Bk / 256, Dk, 2), 256>>>(out);
}

// round 7
// speedup vs baseline: 4.8931x; 1.0196x over previous
#include <cuda_runtime.h>
#include <cstdint>
#include <math.h>

#define Dk 128
#define Bk 1024
#define Rk 131072
#define NN 10
#define BN (Bk * NN)          // 10240
#define RNG 8                 // column ranges (stage-1 grid.x)
#define RSPAN (Rk / RNG)      // 16384 cols per CTA
#define SUB 128               // cols per sub-chunk
#define NSUB (RSPAN / SUB)    // 128
#define JBLK 16               // stage-2 j blocks
#define JW 640                // j per stage-2 block

typedef unsigned long long u64;
typedef unsigned int u32;
typedef unsigned short u16;

// ---------------- device scratch ----------------
__device__ float g_feat[2][Bk * Dk];          // normalized fp32 feats [row][d]
__device__ u32   g_featQ[2][32][Bk];          // int8 feats packed [kc][row]
__device__ u32   g_qQ[2][32][Rk];             // int8 queue packed [kc][r]
__device__ float g_qscale[2][Rk];             // per-column maxabs
__device__ float g_qmul[2][Rk];               // 127/maxabs
__device__ float g_candV[2][Bk * RNG * NN];   // sorted desc per (row,range)
__device__ int   g_candI[2][Bk * RNG * NN];
__device__ int   g_topk[2][Bk * NN];
__device__ float g_nnT[2][Dk * BN];           // gathered fp32 [d][j]
__device__ float g_pS[2][Bk][JBLK];
__device__ float g_pP[2][Bk][JBLK];

// ---------------- helpers ----------------
__device__ __forceinline__ void ffma2(u64 &d, u64 a, u64 b) {
    asm("fma.rn.f32x2 %0, %1, %2, %0;" : "+l"(d) : "l"(a), "l"(b));
}
__device__ __forceinline__ u64 dupf(float f) {
    u64 r; unsigned u = __float_as_uint(f);
    asm("mov.b64 %0, {%1, %2};" : "=l"(r) : "r"(u), "r"(u));
    return r;
}
__device__ __forceinline__ float2 unpack2(u64 a) {
    float2 o;
    asm("mov.b64 {%0, %1}, %2;" : "=f"(o.x), "=f"(o.y) : "l"(a));
    return o;
}
__device__ __forceinline__ u32 smem_u32(const void* p) {
    u32 a;
    asm("{ .reg .u64 t; cvta.to.shared.u64 t, %1; cvt.u32.u64 %0, t; }"
        : "=r"(a) : "l"(p));
    return a;
}
#define CP_ASYNC16(sdst, gsrc) \
    asm volatile("cp.async.cg.shared.global [%0], [%1], 16;" \
                 :: "r"(sdst), "l"(gsrc) : "memory")
#define CP_COMMIT() asm volatile("cp.async.commit_group;" ::: "memory")
#define CP_WAIT1()  asm volatile("cp.async.wait_group 1;" ::: "memory")

// ---------------- 1. normalize rows + int8 pack ---------------------------------
__global__ void normalize_kernel(const float* __restrict__ fX,
                                 const float* __restrict__ fY) {
    int side = blockIdx.y;
    int row = blockIdx.x;
    int d = threadIdx.x;
    const float* in = side ? fY : fX;
    float v = in[row * Dk + d];
    float sq = v * v;
    #pragma unroll
    for (int o = 16; o; o >>= 1) sq += __shfl_xor_sync(0xFFFFFFFFu, sq, o);
    __shared__ float ws[4], wm[4];
    __shared__ float nrm, smx;
    __shared__ unsigned char sb8[128];
    if ((d & 31) == 0) ws[d >> 5] = sq;
    __syncthreads();
    if (d == 0) nrm = sqrtf(ws[0] + ws[1] + ws[2] + ws[3]);
    __syncthreads();
    float nv = v / nrm;
    g_feat[side][row * Dk + d] = nv;
    float av = fabsf(nv);
    #pragma unroll
    for (int o = 16; o; o >>= 1) av = fmaxf(av, __shfl_xor_sync(0xFFFFFFFFu, av, o));
    if ((d & 31) == 0) wm[d >> 5] = av;
    __syncthreads();
    if (d == 0) smx = fmaxf(fmaxf(wm[0], wm[1]), fmaxf(wm[2], wm[3]));
    __syncthreads();
    int q = __float2int_rn(nv * (127.f / smx));
    sb8[d] = (unsigned char)(signed char)q;
    __syncthreads();
    if (d < 32) {
        u32 p = (u32)sb8[4 * d] | ((u32)sb8[4 * d + 1] << 8) |
                ((u32)sb8[4 * d + 2] << 16) | ((u32)sb8[4 * d + 3] << 24);
        g_featQ[side][d][row] = p;
    }
}

// ---------------- 2a. per-column maxabs of queue --------------------------------
__global__ void colmax_kernel(const float* __restrict__ qX,
                              const float* __restrict__ qY) {
    int side = blockIdx.y;
    const float* src = side ? qX : qY;   // side 0 (feat X) uses queue_Y
    int c = blockIdx.x * 256 + threadIdx.x;
    float mx = 1e-12f;
    for (int d = 0; d < Dk; ++d)
        mx = fmaxf(mx, fabsf(src[(size_t)d * Rk + c]));
    g_qscale[side][c] = mx;
    g_qmul[side][c] = 127.f / mx;
}

// ---------------- 2b. transpose + int8 quantize queue ---------------------------
__global__ void transposeQ_kernel(const float* __restrict__ qX,
                                  const float* __restrict__ qY) {
    int side = blockIdx.z;
    const float* src = side ? qX : qY;
    __shared__ float tile[32][33];
    int r0 = blockIdx.x * 32, d0 = blockIdx.y * 32;
    int tx = threadIdx.x, ty = threadIdx.y;
    #pragma unroll
    for (int i = 0; i < 4; ++i)
        tile[ty + i * 8][tx] = src[(size_t)(d0 + ty + i * 8) * Rk + r0 + tx];
    __syncthreads();
    float mul = g_qmul[side][r0 + tx];
    u32 p = 0;
    #pragma unroll
    for (int b = 0; b < 4; ++b) {
        int q = __float2int_rn(tile[ty * 4 + b][tx] * mul);
        p |= ((u32)(unsigned char)(signed char)q) << (8 * b);
    }
    g_qQ[side][(d0 >> 2) + ty][r0 + tx] = p;
}

// ---------------- 3. DP4A sim GEMM + persistent per-row top-10 ------------------
// CTA = 64 rows x 16384-col range. 256 threads (16x16), loop 128 sub-chunks of 128.
// Qs/SC double-buffered via cp.async; top-10 lists persist across the range.
#define S_QS 0                        // Qs u32 [2][kc][128] = 32768 B
#define S_SC 32768                    // SC f [2][128]       = 1024 B
#define S_AS 33792                    // As u32 [kc][64]     = 8192 B
#define S_SS 41984                    // Ss [64][132] f      = 33792 B
#define S_CV 75776                    // 256*11 f            = 11264 B
#define S_CI 87040                    // 256*11 u16          = 5632 B
#define SMEM1 92672
#define SP1 132
#define LP 11

__global__ void __launch_bounds__(256, 2) simtopk_i8_kernel() {
    extern __shared__ char sm[];
    u32 sb = smem_u32(sm);
    u32*   Qs = reinterpret_cast<u32*>(sm + S_QS);
    float* SC = reinterpret_cast<float*>(sm + S_SC);
    u32*   As = reinterpret_cast<u32*>(sm + S_AS);
    float* Ss = reinterpret_cast<float*>(sm + S_SS);
    float* Cv = reinterpret_cast<float*>(sm + S_CV);
    u16*   Ci = reinterpret_cast<u16*>(sm + S_CI);
    int t = threadIdx.x, tx = t & 15, ty = t >> 4;
    int range = blockIdx.x, rt = blockIdx.y, side = blockIdx.z;
    int colBase = range * RSPAN;

    // A tile once: 32 kc x 64 rows
    for (int i = t; i < 512; i += 256) {
        int kc = i >> 4, r4 = i & 15;
        reinterpret_cast<uint4*>(As + kc * 64)[r4] =
            reinterpret_cast<const uint4*>(&g_featQ[side][kc][rt * 64])[r4];
    }
    // init persistent lists (one per thread)
    #pragma unroll
    for (int k = 0; k < NN; ++k) { Cv[t * LP + k] = -1e30f; Ci[t * LP + k] = 0xffff; }
    float tv9 = -1e30f;

    // per-thread cp.async slots: 4 x 16B of Qs, 1 x 16B of SC (t<32)
    int kcA = (t * 4) >> 5;          // = t >> 3
    int c4A = (t * 4) & 31;
    const char* gQbase = reinterpret_cast<const char*>(&g_qQ[side][0][0]);
    size_t qRowStride = (size_t)Rk * 4;        // bytes per kc row
    u32 sQ0 = sb + S_QS + (u32)(kcA * 512 + c4A * 16);
    u32 sSC = sb + S_SC + (u32)(t * 16);

    // prefetch tile 0 into buf 0
    {
        const char* gsrc = gQbase + (size_t)kcA * qRowStride + (size_t)(colBase + c4A * 4) * 4;
        #pragma unroll
        for (int j = 0; j < 4; ++j)
            CP_ASYNC16(sQ0 + j * 16, gsrc + j * 16);
        if (t < 32)
            CP_ASYNC16(sSC, reinterpret_cast<const char*>(&g_qscale[side][colBase]) + t * 16);
        CP_COMMIT();
    }

    int row = t >> 2, seg = t & 3;
    float* myCv = Cv + t * LP;
    u16*   myCi = Ci + t * LP;

    for (int sc = 0; sc < NSUB; ++sc) {
        int buf = sc & 1;
        // prefetch next tile into alternate buffer
        if (sc + 1 < NSUB) {
            int nb = buf ^ 1;
            const char* gsrc = gQbase + (size_t)kcA * qRowStride +
                               (size_t)(colBase + (sc + 1) * SUB + c4A * 4) * 4;
            u32 sdst = sQ0 + (u32)(nb * 16384);
            #pragma unroll
            for (int j = 0; j < 4; ++j)
                CP_ASYNC16(sdst + j * 16, gsrc + j * 16);
            if (t < 32)
                CP_ASYNC16(sSC + (u32)(nb * 512),
                           reinterpret_cast<const char*>(
                               &g_qscale[side][colBase + (sc + 1) * SUB]) + t * 16);
        }
        CP_COMMIT();
        CP_WAIT1();
        __syncthreads();   // tile sc visible to all; prev scan's Ss reads done

        const u32*   Qb = Qs + buf * 4096;
        const float* Sb = SC + buf * 128;

        // mainloop: 4 rows x 8 cols per thread
        int acc[4][8];
        #pragma unroll
        for (int r = 0; r < 4; ++r)
            #pragma unroll
            for (int c = 0; c < 8; ++c) acc[r][c] = 0;
        #pragma unroll 4
        for (int kc = 0; kc < 32; ++kc) {
            int f[4];
            #pragma unroll
            for (int r = 0; r < 4; ++r) f[r] = (int)As[kc * 64 + ty * 4 + r];
            #pragma unroll
            for (int g = 0; g < 2; ++g) {
                uint4 q = *reinterpret_cast<const uint4*>(Qb + kc * 128 + g * 64 + tx * 4);
                #pragma unroll
                for (int r = 0; r < 4; ++r) {
                    acc[r][g * 4 + 0] = __dp4a((int)q.x, f[r], acc[r][g * 4 + 0]);
                    acc[r][g * 4 + 1] = __dp4a((int)q.y, f[r], acc[r][g * 4 + 1]);
                    acc[r][g * 4 + 2] = __dp4a((int)q.z, f[r], acc[r][g * 4 + 2]);
                    acc[r][g * 4 + 3] = __dp4a((int)q.w, f[r], acc[r][g * 4 + 3]);
                }
            }
        }

        // scaled sims to Ss
        #pragma unroll
        for (int g = 0; g < 2; ++g) {
            float4 s = *reinterpret_cast<const float4*>(Sb + g * 64 + tx * 4);
            #pragma unroll
            for (int r = 0; r < 4; ++r) {
                float4 w = make_float4((float)acc[r][g * 4 + 0] * s.x,
                                       (float)acc[r][g * 4 + 1] * s.y,
                                       (float)acc[r][g * 4 + 2] * s.z,
                                       (float)acc[r][g * 4 + 3] * s.w);
                *reinterpret_cast<float4*>(Ss + (ty * 4 + r) * SP1 + g * 64 + tx * 4) = w;
            }
        }
        __syncthreads();   // Ss writes visible

        // scan: thread owns (row, seg), cols seg+4i, persistent list
        {
            const float* sp = Ss + row * SP1;
            u16 ib = (u16)(sc * SUB);
            #pragma unroll 4
            for (int i = 0; i < 32; ++i) {
                int col = seg + 4 * i;
                float v = sp[col];
                if (v > tv9) {
                    int p = NN - 1;
                    while (p > 0 && myCv[p - 1] < v) {
                        myCv[p] = myCv[p - 1]; myCi[p] = myCi[p - 1]; --p;
                    }
                    myCv[p] = v; myCi[p] = (u16)(ib + col);
                    tv9 = myCv[NN - 1];
                }
            }
        }
    }
    __syncthreads();

    // merge 4 seg-lists per row -> sorted top-10 -> g_cand
    if (t < 64) {
        float* mv = Ss + t * 16;
        int*   mi = reinterpret_cast<int*>(Ss + 1024 + t * 16);
        #pragma unroll
        for (int k = 0; k < NN; ++k) { mv[k] = -1e30f; mi[k] = 0x7fffffff; }
        float m9 = -1e30f; int i9 = 0x7fffffff;
        for (int s = 0; s < 4; ++s) {
            const float* cv = Cv + (t * 4 + s) * LP;
            const u16*   ci = Ci + (t * 4 + s) * LP;
            for (int k = 0; k < NN; ++k) {
                float v = cv[k];
                if (v < m9) break;
                int id = (int)ci[k];
                if (v == m9 && id >= i9) continue;
                int p = NN - 1;
                while (p > 0 && (mv[p - 1] < v ||
                                 (mv[p - 1] == v && mi[p - 1] > id))) {
                    mv[p] = mv[p - 1]; mi[p] = mi[p - 1]; --p;
                }
                mv[p] = v; mi[p] = id;
                m9 = mv[NN - 1]; i9 = mi[NN - 1];
            }
        }
        size_t gb = (((size_t)(rt * 64 + t) * RNG) + range) * NN;
        #pragma unroll
        for (int k = 0; k < NN; ++k) {
            g_candV[side][gb + k] = mv[k];
            g_candI[side][gb + k] = colBase + mi[k];
        }
    }
}

// ---------------- 4. per-row 8-way heads merge -> final top-10 ------------------
__global__ void topk_merge_kernel() {
    __shared__ float cv[64 * 80];
    __shared__ int   ci[64 * 80];
    int b = blockIdx.x, side = blockIdx.y, t = threadIdx.x;  // 64 threads
    int row0 = b * 64;
    for (int i = t; i < 64 * 80; i += 64) {
        cv[i] = g_candV[side][(size_t)row0 * 80 + i];
        ci[i] = g_candI[side][(size_t)row0 * 80 + i];
    }
    __syncthreads();
    const float* v = cv + t * 80;
    const int*   id = ci + t * 80;
    int cur[8];
    #pragma unroll
    for (int h = 0; h < 8; ++h) cur[h] = h * 10;
    for (int k = 0; k < NN; ++k) {
        float best = -1e38f; int bi = 0x7fffffff; int bh = 0;
        #pragma unroll
        for (int h = 0; h < 8; ++h) {
            int c = cur[h];
            if (c < h * 10 + 10) {
                float x = v[c];
                int xi = id[c];
                if (x > best || (x == best && xi < bi)) { best = x; bi = xi; bh = h; }
            }
        }
        g_topk[side][(row0 + t) * NN + k] = bi;
        #pragma unroll
        for (int h = 0; h < 8; ++h) cur[h] += (h == bh);
    }
}

// ---------------- 5. gather neighbor columns (exact fp32) -----------------------
__global__ void gather_kernel(const float* __restrict__ qX,
                              const float* __restrict__ qY) {
    int j = blockIdx.x * 256 + threadIdx.x;
    int d = blockIdx.y;
    int side = blockIdx.z;
    const float* Q = side ? qX : qY;
    int c = g_topk[side][j];
    g_nnT[side][d * BN + j] = Q[(size_t)d * Rk + c];
}

// ---------------- 6. stage-2 logits GEMM + fixed-max partial LSE ----------------
#define FP 132
#define SM2_F 0
#define SM2_J (64 * FP)
#define SM2_S (SM2_J + 128 * 64)
#define SM2_P (SM2_S + 64)
#define SMEM2_BYTES ((SM2_P + 64) * 4)

__global__ void __launch_bounds__(256, 3) lse_gemm_kernel() {
    extern __shared__ float s2[];
    float* F = s2 + SM2_F;
    float* J = s2 + SM2_J;
    float* accS = s2 + SM2_S;
    float* accP = s2 + SM2_P;
    int t = threadIdx.x;
    int tx = t & 15, ty = t >> 4;
    int rg = blockIdx.x, jb = blockIdx.y, side = blockIdx.z;

    {
        const float* feat = g_feat[side] + rg * 64 * Dk;
        for (int i = t; i < 64 * Dk; i += 256) {
            int r = i >> 7, d = i & 127;
            F[r * FP + d] = feat[i];
        }
        if (t < 64) { accS[t] = 0.f; accP[t] = 0.f; }
    }
    __syncthreads();

    const float4* nn4 = reinterpret_cast<const float4*>(g_nnT[side]);
    for (int jt = 0; jt < JW / 64; ++jt) {
        float4* J4 = reinterpret_cast<float4*>(J);
        #pragma unroll
        for (int i = 0; i < 8; ++i) {
            int lin = i * 256 + t;
            int d = lin >> 4, c4 = lin & 15;
            J4[d * 16 + c4] = nn4[(size_t)d * (BN / 4) + jb * (JW / 4) + jt * 16 + c4];
        }
        __syncthreads();

        u64 acc[4][2];
        #pragma unroll
        for (int r = 0; r < 4; ++r) { acc[r][0] = 0ull; acc[r][1] = 0ull; }
        const float* fb = F + (ty * 4) * FP;
        #pragma unroll 8
        for (int d = 0; d < Dk; ++d) {
            ulonglong2 q = *reinterpret_cast<const ulonglong2*>(J + d * 64 + tx * 4);
            #pragma unroll
            for (int r = 0; r < 4; ++r) {
                u64 fd = dupf(fb[r * FP + d]);
                ffma2(acc[r][0], q.x, fd);
                ffma2(acc[r][1], q.y, fd);
            }
        }

        int j0 = jb * JW + jt * 64 + tx * 4;
        #pragma unroll
        for (int r = 0; r < 4; ++r) {
            float2 a = unpack2(acc[r][0]);
            float2 b2 = unpack2(acc[r][1]);
            float vv[4] = { a.x, a.y, b2.x, b2.y };
            int rowg = rg * 64 + ty * 4 + r;
            float sE = 0.f, sP = 0.f;
            #pragma unroll
            for (int i = 0; i < 4; ++i) {
                float lg = vv[i] * 10.f;            // / TEMP
                sE += __expf(lg - 10.f);            // fixed max = 10 (cos<=1)
                unsigned dj = (unsigned)(j0 + i - rowg * NN);
                if (dj < (unsigned)NN) sP += lg;
            }
            #pragma unroll
            for (int o = 8; o; o >>= 1) {
                sE += __shfl_xor_sync(0xFFFFFFFFu, sE, o);
                sP += __shfl_xor_sync(0xFFFFFFFFu, sP, o);
            }
            if (tx == 0) { accS[ty * 4 + r] += sE; accP[ty * 4 + r] += sP; }
        }
        __syncthreads();
    }
    if (t < 64) {
        int rowg = rg * 64 + t;
        g_pS[side][rowg][jb] = accS[t];
        g_pP[side][rowg][jb] = accP[t];
    }
}

// ---------------- 7. combine partials -> loss ------------------------------------
__global__ void combine_kernel(float* __restrict__ out) {
    __shared__ float red[1024];
    int t = threadIdx.x;
    float term = 0.f;
    #pragma unroll
    for (int side = 0; side < 2; ++side) {
        float S = 0.f, P = 0.f;
        #pragma unroll
        for (int jb = 0; jb < JBLK; ++jb) { S += g_pS[side][t][jb]; P += g_pP[side][t][jb]; }
        term += P - (float)NN * (10.f + logf(S));
    }
    red[t] = term;
    __syncthreads();
    for (int s = 512; s; s >>= 1) {
        if (t < s) red[t] += red[t + s];
        __syncthreads();
    }
    if (t == 0) out[0] = -red[0] / (float)Bk;
}

// ---------------- 8. queue head columns ------------------------------------------
__global__ void qhead_kernel(float* __restrict__ out) {
    int c = blockIdx.x * 256 + threadIdx.x;
    int d = blockIdx.y;
    int side = blockIdx.z;
    out[1 + (size_t)side * Dk * Rk + (size_t)d * Rk + c] = g_feat[side][c * Dk + d];
}

// ---------------- launch ----------------------------------------------------------
extern "C" void kernel_launch(void* const* d_in, const int* in_sizes, int n_in,
                              void* d_out, int out_size) {
    const float* fX = (const float*)d_in[0];
    const float* fY = (const float*)d_in[1];
    const float* qX = (const float*)d_in[2];
    const float* qY = (const float*)d_in[3];
    float* out = (float*)d_out;

    cudaFuncSetAttribute(simtopk_i8_kernel,
                         cudaFuncAttributeMaxDynamicSharedMemorySize, SMEM1);
    cudaFuncSetAttribute(lse_gemm_kernel,
                         cudaFuncAttributeMaxDynamicSharedMemorySize, SMEM2_BYTES);

    normalize_kernel<<<dim3(Bk, 2, 1), Dk>>>(fX, fY);
    colmax_kernel<<<dim3(Rk / 256, 2, 1), 256>>>(qX, qY);
    transposeQ_kernel<<<dim3(Rk / 32, Dk / 32, 2), dim3(32, 8, 1)>>>(qX, qY);

    simtopk_i8_kernel<<<dim3(RNG, Bk / 64, 2), 256, SMEM1>>>();
    topk_merge_kernel<<<dim3(Bk / 64, 2, 1), 64>>>();
    gather_kernel<<<dim3(BN / 256, Dk, 2), 256>>>(qX, qY);
    lse_gemm_kernel<<<dim3(Bk / 64, JBLK, 2), 256, SMEM2_BYTES>>>();
    combine_kernel<<<1, 1024>>>(out);

    cudaMemcpyAsync(out + 1, qX, (size_t)Dk * Rk * sizeof(float),
                    cudaMemcpyDeviceToDevice, 0);
    cudaMemcpyAsync(out + 1 + (size_t)Dk * Rk, qY, (size_t)Dk * Rk * sizeof(float),
                    cudaMemcpyDeviceToDevice, 0);
    qhead_kernel<<<dim3(Bk / 256, Dk, 2), 256>>>(out);
}